// round 1
// baseline (speedup 1.0000x reference)
#include <cuda_runtime.h>
#include <math.h>

#define N_NODES 20000
#define CDIM 256
#define HHEADS 8
#define DHEAD 32
#define E_EDGES 160000
#define L_LAYERS 4
#define R_REL 2
#define PCOLS 1280   // q(256) | k_r0(256) | k_r1(256) | v_r0(256) | v_r1(256)

// ---------------- scratch (device globals; no allocations allowed) ----------
__device__ float g_P[(size_t)N_NODES * PCOLS];       // projected features per layer
__device__ float g_G[(size_t)N_NODES * CDIM];        // gelu(agg)
__device__ float g_hA[(size_t)N_NODES * CDIM];       // ping
__device__ float g_hB[(size_t)N_NODES * CDIM];       // pong
__device__ float g_Bf[(size_t)L_LAYERS * CDIM * PCOLS]; // folded projection weights
__device__ float g_bfv[(size_t)L_LAYERS * PCOLS];       // folded bias
__device__ int g_deg[N_NODES];
__device__ int g_rowptr[N_NODES + 1];
__device__ int g_cursor[N_NODES];
__device__ int g_eadj[2 * E_EDGES];                  // (src<<1)|rel, grouped by dst

// ---------------- weight folding ----------------
// Bf[l][c][j]:  j<256            -> W_q  = kqv_w[l][c][C + j]
//               j in [256,768)   -> sum_d W_k[c][h*32+d] * krel[l][r][h][d][f]
//               j in [768,1280)  -> sum_d W_v[c][h*32+d] * vrel[l][r][h][d][f]
__global__ void fold_weights(const float* __restrict__ kqv_w,
                             const float* __restrict__ krel,
                             const float* __restrict__ vrel) {
    long idx = (long)blockIdx.x * blockDim.x + threadIdx.x;
    const long total = (long)L_LAYERS * CDIM * PCOLS;
    if (idx >= total) return;
    int j = (int)(idx % PCOLS);
    int c = (int)((idx / PCOLS) % CDIM);
    int l = (int)(idx / ((long)PCOLS * CDIM));
    const float* W = kqv_w + ((long)l * CDIM + c) * (3 * CDIM);
    float val;
    if (j < CDIM) {
        val = W[CDIM + j];  // q columns (split order is k,q,v)
    } else {
        int jj = j - CDIM;
        int sec = jj >> 8;      // 0,1 -> k rel0/1 ; 2,3 -> v rel0/1
        int r = sec & 1;
        int isv = sec >> 1;
        int hf = jj & 255;
        int h = hf >> 5, f = hf & 31;
        const float* M = (isv ? vrel : krel) +
                         ((((long)l * R_REL + r) * HHEADS + h) * DHEAD) * DHEAD + f;
        const float* wk = W + (isv ? 2 * CDIM : 0) + h * DHEAD;
        float s = 0.f;
#pragma unroll
        for (int d = 0; d < DHEAD; d++) s += wk[d] * M[(long)d * DHEAD];
        val = s;
    }
    g_Bf[idx] = val;
}

__global__ void fold_bias(const float* __restrict__ kqv_b,
                          const float* __restrict__ krel,
                          const float* __restrict__ vrel) {
    int idx = blockIdx.x * blockDim.x + threadIdx.x;
    if (idx >= L_LAYERS * PCOLS) return;
    int j = idx % PCOLS;
    int l = idx / PCOLS;
    const float* b = kqv_b + (long)l * 3 * CDIM;
    float val;
    if (j < CDIM) {
        val = b[CDIM + j];
    } else {
        int jj = j - CDIM;
        int sec = jj >> 8;
        int r = sec & 1;
        int isv = sec >> 1;
        int hf = jj & 255;
        int h = hf >> 5, f = hf & 31;
        const float* M = (isv ? vrel : krel) +
                         ((((long)l * R_REL + r) * HHEADS + h) * DHEAD) * DHEAD + f;
        const float* bk = b + (isv ? 2 * CDIM : 0) + h * DHEAD;
        float s = 0.f;
#pragma unroll
        for (int d = 0; d < DHEAD; d++) s += bk[d] * M[(long)d * DHEAD];
        val = s;
    }
    g_bfv[idx] = val;
}

// ---------------- CSR build ----------------
__global__ void zero_deg() {
    int i = blockIdx.x * blockDim.x + threadIdx.x;
    if (i < N_NODES) g_deg[i] = 0;
}

__global__ void hist_kernel(const int* __restrict__ ei0, const int* __restrict__ ei1) {
    int i = blockIdx.x * blockDim.x + threadIdx.x;
    if (i >= 2 * E_EDGES) return;
    int dst = (i < E_EDGES) ? ei0[E_EDGES + i] : ei1[E_EDGES + (i - E_EDGES)];
    atomicAdd(&g_deg[dst], 1);
}

__global__ void scan_kernel() {
    __shared__ int sh[1024];
    __shared__ int carry;
    int tid = threadIdx.x;
    if (tid == 0) { carry = 0; g_rowptr[0] = 0; }
    __syncthreads();
    for (int base = 0; base < N_NODES; base += 1024) {
        int i = base + tid;
        int v = (i < N_NODES) ? g_deg[i] : 0;
        sh[tid] = v;
        __syncthreads();
        for (int off = 1; off < 1024; off <<= 1) {
            int t = (tid >= off) ? sh[tid - off] : 0;
            __syncthreads();
            sh[tid] += t;
            __syncthreads();
        }
        int inc = sh[tid] + carry;
        if (i < N_NODES) { g_rowptr[i + 1] = inc; g_cursor[i] = inc - v; }
        __syncthreads();
        if (tid == 1023) carry = inc;
        __syncthreads();
    }
}

__global__ void scatter_kernel(const int* __restrict__ ei0, const int* __restrict__ ei1) {
    int i = blockIdx.x * blockDim.x + threadIdx.x;
    if (i >= 2 * E_EDGES) return;
    int r = (i < E_EDGES) ? 0 : 1;
    int e = r ? (i - E_EDGES) : i;
    const int* ei = r ? ei1 : ei0;
    int src = ei[e];
    int dst = ei[E_EDGES + e];
    int pos = atomicAdd(&g_cursor[dst], 1);
    g_eadj[pos] = (src << 1) | r;
}

// ---------------- GEMM: C = A[MxK] * B[KxN] + bias; optional skip blend ------
// 128x128 tile, BK=16, 256 threads, 8x8 per thread.
__global__ __launch_bounds__(256) void gemm128(
    const float* __restrict__ A, const float* __restrict__ B,
    const float* __restrict__ bias, float* __restrict__ Cmat,
    int M, int N, int K,
    const float* __restrict__ prev, const float* __restrict__ skipp)
{
    __shared__ float As[16][128];
    __shared__ float Bs[16][128];
    const int tid = threadIdx.x;
    const int brow = blockIdx.y * 128;
    const int bcol = blockIdx.x * 128;
    const int a_row = tid >> 2;
    const int a_k4 = (tid & 3) * 4;
    const int b_k = tid >> 5;
    const int b_c4 = (tid & 31) * 4;
    const int ty = tid >> 4, tx = tid & 15;

    float acc[8][8];
#pragma unroll
    for (int i = 0; i < 8; i++)
#pragma unroll
        for (int j = 0; j < 8; j++) acc[i][j] = 0.f;

    for (int k0 = 0; k0 < K; k0 += 16) {
#pragma unroll
        for (int p = 0; p < 2; p++) {
            int r = a_row + p * 64;
            int grow = brow + r;
            float4 v = make_float4(0.f, 0.f, 0.f, 0.f);
            if (grow < M) v = *(const float4*)(A + (long)grow * K + k0 + a_k4);
            As[a_k4 + 0][r] = v.x; As[a_k4 + 1][r] = v.y;
            As[a_k4 + 2][r] = v.z; As[a_k4 + 3][r] = v.w;
        }
#pragma unroll
        for (int p = 0; p < 2; p++) {
            int kk = b_k + p * 8;
            float4 v = *(const float4*)(B + (long)(k0 + kk) * N + bcol + b_c4);
            *(float4*)&Bs[kk][b_c4] = v;
        }
        __syncthreads();
#pragma unroll
        for (int kk = 0; kk < 16; kk++) {
            float a[8], b[8];
            *(float4*)(a)     = *(const float4*)&As[kk][ty * 8];
            *(float4*)(a + 4) = *(const float4*)&As[kk][ty * 8 + 4];
            *(float4*)(b)     = *(const float4*)&Bs[kk][tx * 8];
            *(float4*)(b + 4) = *(const float4*)&Bs[kk][tx * 8 + 4];
#pragma unroll
            for (int i = 0; i < 8; i++)
#pragma unroll
                for (int j = 0; j < 8; j++) acc[i][j] += a[i] * b[j];
        }
        __syncthreads();
    }

    float s = 1.f, oms = 0.f;
    if (skipp) { float sk = *skipp; s = 1.f / (1.f + __expf(-sk)); oms = 1.f - s; }

#pragma unroll
    for (int i = 0; i < 8; i++) {
        int grow = brow + ty * 8 + i;
        if (grow >= M) break;
#pragma unroll
        for (int j = 0; j < 8; j += 4) {
            int gcol = bcol + tx * 8 + j;
            float4 o;
            o.x = acc[i][j + 0] + bias[gcol + 0];
            o.y = acc[i][j + 1] + bias[gcol + 1];
            o.z = acc[i][j + 2] + bias[gcol + 2];
            o.w = acc[i][j + 3] + bias[gcol + 3];
            if (prev) {
                const float4 pv = *(const float4*)(prev + (long)grow * N + gcol);
                o.x = s * o.x + oms * pv.x;
                o.y = s * o.y + oms * pv.y;
                o.z = s * o.z + oms * pv.z;
                o.w = s * o.w + oms * pv.w;
            }
            *(float4*)(Cmat + (long)grow * N + gcol) = o;
        }
    }
}

// ---------------- edge aggregation: warp per dst node, online softmax --------
__global__ __launch_bounds__(256) void edge_agg(const float* __restrict__ prel_l) {
    int warp = (blockIdx.x * blockDim.x + threadIdx.x) >> 5;
    int lane = threadIdx.x & 31;
    if (warp >= N_NODES) return;
    const int n = warp;
    const int h = lane >> 2;
    const int q8 = (lane & 3) * 8;

    const float* qp = g_P + (long)n * PCOLS + h * DHEAD + q8;
    float4 q0 = *(const float4*)qp;
    float4 q1 = *(const float4*)(qp + 4);
    const float scale = 0.17677669529663687f;  // 1/sqrt(32)
    const float p0 = prel_l[h] * scale;
    const float p1 = prel_l[HHEADS + h] * scale;

    float m = -INFINITY, ssum = 0.f;
    float acc[8];
#pragma unroll
    for (int i = 0; i < 8; i++) acc[i] = 0.f;

    const int e0 = g_rowptr[n], e1 = g_rowptr[n + 1];
    for (int e = e0; e < e1; e++) {
        int pk = g_eadj[e];
        int r = pk & 1;
        int src = pk >> 1;
        const float* base = g_P + (long)src * PCOLS;
        const float* kp = base + CDIM + r * CDIM + h * DHEAD + q8;
        const float* vp = base + 3 * CDIM + r * CDIM + h * DHEAD + q8;
        float4 k0 = *(const float4*)kp;
        float4 k1 = *(const float4*)(kp + 4);
        float4 v0 = *(const float4*)vp;
        float4 v1 = *(const float4*)(vp + 4);
        float d = q0.x * k0.x + q0.y * k0.y + q0.z * k0.z + q0.w * k0.w
                + q1.x * k1.x + q1.y * k1.y + q1.z * k1.z + q1.w * k1.w;
        d += __shfl_xor_sync(0xffffffffu, d, 1);
        d += __shfl_xor_sync(0xffffffffu, d, 2);
        float lg = d * (r ? p1 : p0);
        float nm = fmaxf(m, lg);
        float cf = __expf(m - nm);   // m=-inf on first edge -> 0
        float p = __expf(lg - nm);
        ssum = ssum * cf + p;
        m = nm;
        acc[0] = acc[0] * cf + p * v0.x;
        acc[1] = acc[1] * cf + p * v0.y;
        acc[2] = acc[2] * cf + p * v0.z;
        acc[3] = acc[3] * cf + p * v0.w;
        acc[4] = acc[4] * cf + p * v1.x;
        acc[5] = acc[5] * cf + p * v1.y;
        acc[6] = acc[6] * cf + p * v1.z;
        acc[7] = acc[7] * cf + p * v1.w;
    }

    float inv = 1.0f / fmaxf(ssum, 1e-16f);
    float out[8];
#pragma unroll
    for (int i = 0; i < 8; i++) {
        float xg = acc[i] * inv;                               // agg (0 if no edges)
        out[i] = 0.5f * xg * (1.0f + erff(xg * 0.70710678118654752f));  // exact gelu
    }
    float* gp = g_G + (long)n * CDIM + h * DHEAD + q8;
    *(float4*)gp       = make_float4(out[0], out[1], out[2], out[3]);
    *(float4*)(gp + 4) = make_float4(out[4], out[5], out[6], out[7]);
}

// ---------------- fused relu + layernorm (warp per row, in place) -----------
__global__ __launch_bounds__(256) void relu_ln(float* __restrict__ hbuf,
                                               const float* __restrict__ g,
                                               const float* __restrict__ b) {
    int warp = (blockIdx.x * blockDim.x + threadIdx.x) >> 5;
    int lane = threadIdx.x & 31;
    if (warp >= N_NODES) return;
    float* row = hbuf + (long)warp * CDIM;
    float v[8];
    *(float4*)(v)     = *(const float4*)(row + lane * 8);
    *(float4*)(v + 4) = *(const float4*)(row + lane * 8 + 4);
    float s = 0.f, s2 = 0.f;
#pragma unroll
    for (int i = 0; i < 8; i++) {
        v[i] = fmaxf(v[i], 0.f);
        s += v[i];
        s2 += v[i] * v[i];
    }
#pragma unroll
    for (int off = 16; off > 0; off >>= 1) {
        s += __shfl_xor_sync(0xffffffffu, s, off);
        s2 += __shfl_xor_sync(0xffffffffu, s2, off);
    }
    float mu = s * (1.f / CDIM);
    float var = s2 * (1.f / CDIM) - mu * mu;
    float rs = rsqrtf(var + 1e-5f);
#pragma unroll
    for (int i = 0; i < 8; i++) {
        int c = lane * 8 + i;
        v[i] = (v[i] - mu) * rs * g[c] + b[c];
    }
    *(float4*)(row + lane * 8)     = *(const float4*)(v);
    *(float4*)(row + lane * 8 + 4) = *(const float4*)(v + 4);
}

// ---------------- launch ----------------
extern "C" void kernel_launch(void* const* d_in, const int* in_sizes, int n_in,
                              void* d_out, int out_size) {
    const float* x      = (const float*)d_in[0];
    const int*   ei0    = (const int*)d_in[1];
    const int*   ei1    = (const int*)d_in[2];
    const float* kqv_w  = (const float*)d_in[3];
    const float* kqv_b  = (const float*)d_in[4];
    const float* out_w  = (const float*)d_in[5];
    const float* out_b  = (const float*)d_in[6];
    const float* skip   = (const float*)d_in[7];
    const float* krel   = (const float*)d_in[8];
    const float* vrel   = (const float*)d_in[9];
    const float* prel   = (const float*)d_in[10];
    const float* ln_g   = (const float*)d_in[11];
    const float* ln_b   = (const float*)d_in[12];
    float* out = (float*)d_out;

    float *hA, *hB, *Bf, *bf;
    cudaGetSymbolAddress((void**)&hA, g_hA);
    cudaGetSymbolAddress((void**)&hB, g_hB);
    cudaGetSymbolAddress((void**)&Bf, g_Bf);
    cudaGetSymbolAddress((void**)&bf, g_bfv);

    // Preprocess: fold weights, build CSR (once per launch)
    {
        long total = (long)L_LAYERS * CDIM * PCOLS;
        fold_weights<<<(int)((total + 255) / 256), 256>>>(kqv_w, krel, vrel);
        fold_bias<<<(L_LAYERS * PCOLS + 255) / 256, 256>>>(kqv_b, krel, vrel);
        zero_deg<<<(N_NODES + 255) / 256, 256>>>();
        hist_kernel<<<(2 * E_EDGES + 255) / 256, 256>>>(ei0, ei1);
        scan_kernel<<<1, 1024>>>();
        scatter_kernel<<<(2 * E_EDGES + 255) / 256, 256>>>(ei0, ei1);
    }

    const float* hin = x;
    for (int l = 0; l < L_LAYERS; l++) {
        float* hout = (l == 3) ? out : ((l % 2 == 0) ? hA : hB);

        // GEMM1: P = hin @ Bf[l] + bf[l]  -> [N, 1280]
        {
            float* P;
            cudaGetSymbolAddress((void**)&P, g_P);
            dim3 grid(PCOLS / 128, (N_NODES + 127) / 128);
            gemm128<<<grid, 256>>>(hin, Bf + (long)l * CDIM * PCOLS,
                                   bf + (long)l * PCOLS, P,
                                   N_NODES, PCOLS, CDIM, nullptr, nullptr);
        }

        // Edge aggregation + softmax + gelu -> g_G
        edge_agg<<<(N_NODES * 32) / 256, 256>>>(prel + (long)l * R_REL * HHEADS);

        // GEMM2: hout = s*(G @ out_w[l] + out_b[l]) + (1-s)*hin
        {
            float* G;
            cudaGetSymbolAddress((void**)&G, g_G);
            dim3 grid(CDIM / 128, (N_NODES + 127) / 128);
            gemm128<<<grid, 256>>>(G, out_w + (long)l * CDIM * CDIM,
                                   out_b + (long)l * CDIM, hout,
                                   N_NODES, CDIM, CDIM, hin, skip + l);
        }

        if (l < L_LAYERS - 1) {
            relu_ln<<<(N_NODES * 32) / 256, 256>>>(hout, ln_g + (long)l * CDIM,
                                                   ln_b + (long)l * CDIM);
        }
        hin = hout;
    }
}

// round 3
// speedup vs baseline: 1.7996x; 1.7996x over previous
#include <cuda_runtime.h>
#include <cuda_bf16.h>
#include <math.h>
#include <stdint.h>

#define N_NODES 20000
#define CDIM 256
#define HHEADS 8
#define DHEAD 32
#define E_EDGES 160000
#define L_LAYERS 4
#define R_REL 2
#define PCOLS 1280   // q(256) | k_r0(256) | k_r1(256) | v_r0(256) | v_r1(256)
#define KTOT 256

// ===================== scratch (device globals) =============================
__device__ float g_P[(size_t)N_NODES * PCOLS];
__device__ float g_G[(size_t)N_NODES * CDIM];
__device__ float g_hA[(size_t)N_NODES * CDIM];
__device__ float g_hB[(size_t)N_NODES * CDIM];
__device__ float g_bfv[(size_t)L_LAYERS * PCOLS];
__device__ __nv_bfloat16 g_W1hi[(size_t)L_LAYERS * PCOLS * CDIM];  // [l][n][k]
__device__ __nv_bfloat16 g_W1lo[(size_t)L_LAYERS * PCOLS * CDIM];
__device__ __nv_bfloat16 g_W2hi[(size_t)L_LAYERS * CDIM * CDIM];   // [l][n][k]
__device__ __nv_bfloat16 g_W2lo[(size_t)L_LAYERS * CDIM * CDIM];
__device__ __nv_bfloat16 g_Ahi[(size_t)N_NODES * CDIM];
__device__ __nv_bfloat16 g_Alo[(size_t)N_NODES * CDIM];
__device__ int g_deg[N_NODES];
__device__ int g_rowptr[N_NODES + 1];
__device__ int g_cursor[N_NODES];
__device__ int g_eadj[2 * E_EDGES];

// ===================== small PTX helpers ====================================
__device__ __forceinline__ uint32_t smem_u32(const void* p) {
    uint32_t a;
    asm("{ .reg .u64 t; cvta.to.shared.u64 t, %1; cvt.u32.u64 %0, t; }"
        : "=r"(a) : "l"(p));
    return a;
}
__device__ __forceinline__ void cpasync16(uint32_t dst, const void* src, int src_sz) {
    asm volatile("cp.async.cg.shared.global [%0], [%1], 16, %2;"
                 :: "r"(dst), "l"(src), "r"(src_sz));
}
__device__ __forceinline__ void ldm_x4(uint32_t* r, uint32_t addr) {
    asm volatile("ldmatrix.sync.aligned.m8n8.x4.shared.b16 {%0,%1,%2,%3}, [%4];"
                 : "=r"(r[0]), "=r"(r[1]), "=r"(r[2]), "=r"(r[3]) : "r"(addr));
}
__device__ __forceinline__ void mma_bf16(float* c, const uint32_t* a, const uint32_t* b) {
    asm volatile("mma.sync.aligned.m16n8k16.row.col.f32.bf16.bf16.f32 "
                 "{%0,%1,%2,%3}, {%4,%5,%6,%7}, {%8,%9}, {%0,%1,%2,%3};"
                 : "+f"(c[0]), "+f"(c[1]), "+f"(c[2]), "+f"(c[3])
                 : "r"(a[0]), "r"(a[1]), "r"(a[2]), "r"(a[3]),
                   "r"(b[0]), "r"(b[1]));
}

// ===================== weight folding (transposed, bf16-split) ==============
__global__ void fold_w1(const float* __restrict__ kqv_w,
                        const float* __restrict__ krel,
                        const float* __restrict__ vrel) {
    long idx = (long)blockIdx.x * blockDim.x + threadIdx.x;
    const long total = (long)L_LAYERS * CDIM * PCOLS;
    if (idx >= total) return;
    int j = (int)(idx % PCOLS);
    int c = (int)((idx / PCOLS) % CDIM);
    int l = (int)(idx / ((long)PCOLS * CDIM));
    const float* W = kqv_w + ((long)l * CDIM + c) * (3 * CDIM);
    float val;
    if (j < CDIM) {
        val = W[CDIM + j];  // q (split order is k,q,v)
    } else {
        int jj = j - CDIM;
        int sec = jj >> 8;      // 0,1: k rel0/1; 2,3: v rel0/1
        int r = sec & 1;
        int isv = sec >> 1;
        int hf = jj & 255;
        int h = hf >> 5, f = hf & 31;
        const float* M = (isv ? vrel : krel) +
                         ((((long)l * R_REL + r) * HHEADS + h) * DHEAD) * DHEAD + f;
        const float* wk = W + (isv ? 2 * CDIM : 0) + h * DHEAD;
        float s = 0.f;
#pragma unroll
        for (int d = 0; d < DHEAD; d++) s += wk[d] * M[(long)d * DHEAD];
        val = s;
    }
    __nv_bfloat16 hi = __float2bfloat16(val);
    __nv_bfloat16 lo = __float2bfloat16(val - __bfloat162float(hi));
    long o = ((long)l * PCOLS + j) * CDIM + c;  // transposed [n][k]
    g_W1hi[o] = hi;
    g_W1lo[o] = lo;
}

__global__ void fold_w2(const float* __restrict__ out_w) {
    long idx = (long)blockIdx.x * blockDim.x + threadIdx.x;
    if (idx >= (long)L_LAYERS * CDIM * CDIM) return;
    int n = (int)(idx & 255);
    int k = (int)((idx >> 8) & 255);
    int l = (int)(idx >> 16);
    float val = out_w[((long)l * CDIM + k) * CDIM + n];
    __nv_bfloat16 hi = __float2bfloat16(val);
    __nv_bfloat16 lo = __float2bfloat16(val - __bfloat162float(hi));
    long o = ((long)l * CDIM + n) * CDIM + k;   // transposed [n][k]
    g_W2hi[o] = hi;
    g_W2lo[o] = lo;
}

__global__ void fold_bias(const float* __restrict__ kqv_b,
                          const float* __restrict__ krel,
                          const float* __restrict__ vrel) {
    int idx = blockIdx.x * blockDim.x + threadIdx.x;
    if (idx >= L_LAYERS * PCOLS) return;
    int j = idx % PCOLS;
    int l = idx / PCOLS;
    const float* b = kqv_b + (long)l * 3 * CDIM;
    float val;
    if (j < CDIM) {
        val = b[CDIM + j];
    } else {
        int jj = j - CDIM;
        int sec = jj >> 8;
        int r = sec & 1;
        int isv = sec >> 1;
        int hf = jj & 255;
        int h = hf >> 5, f = hf & 31;
        const float* M = (isv ? vrel : krel) +
                         ((((long)l * R_REL + r) * HHEADS + h) * DHEAD) * DHEAD + f;
        const float* bk = b + (isv ? 2 * CDIM : 0) + h * DHEAD;
        float s = 0.f;
#pragma unroll
        for (int d = 0; d < DHEAD; d++) s += bk[d] * M[(long)d * DHEAD];
        val = s;
    }
    g_bfv[idx] = val;
}

// ===================== activation split fp32 -> bf16 hi/lo ==================
__global__ void split_fp32(const float* __restrict__ src, int n4) {
    int i = blockIdx.x * blockDim.x + threadIdx.x;
    if (i >= n4) return;
    float4 v = ((const float4*)src)[i];
    __nv_bfloat16 h0 = __float2bfloat16(v.x), h1 = __float2bfloat16(v.y);
    __nv_bfloat16 h2 = __float2bfloat16(v.z), h3 = __float2bfloat16(v.w);
    __nv_bfloat162 hi01; hi01.x = h0; hi01.y = h1;
    __nv_bfloat162 hi23; hi23.x = h2; hi23.y = h3;
    __nv_bfloat162 lo01, lo23;
    lo01.x = __float2bfloat16(v.x - __bfloat162float(h0));
    lo01.y = __float2bfloat16(v.y - __bfloat162float(h1));
    lo23.x = __float2bfloat16(v.z - __bfloat162float(h2));
    lo23.y = __float2bfloat16(v.w - __bfloat162float(h3));
    ((__nv_bfloat162*)g_Ahi)[i * 2]     = hi01;
    ((__nv_bfloat162*)g_Ahi)[i * 2 + 1] = hi23;
    ((__nv_bfloat162*)g_Alo)[i * 2]     = lo01;
    ((__nv_bfloat162*)g_Alo)[i * 2 + 1] = lo23;
}

// ===================== CSR build =============================================
__global__ void zero_deg() {
    int i = blockIdx.x * blockDim.x + threadIdx.x;
    if (i < N_NODES) g_deg[i] = 0;
}
__global__ void hist_kernel(const int* __restrict__ ei0, const int* __restrict__ ei1) {
    int i = blockIdx.x * blockDim.x + threadIdx.x;
    if (i >= 2 * E_EDGES) return;
    int dst = (i < E_EDGES) ? ei0[E_EDGES + i] : ei1[E_EDGES + (i - E_EDGES)];
    atomicAdd(&g_deg[dst], 1);
}
__global__ void scan_kernel() {
    __shared__ int sh[1024];
    __shared__ int carry;
    int tid = threadIdx.x;
    if (tid == 0) { carry = 0; g_rowptr[0] = 0; }
    __syncthreads();
    for (int base = 0; base < N_NODES; base += 1024) {
        int i = base + tid;
        int v = (i < N_NODES) ? g_deg[i] : 0;
        sh[tid] = v;
        __syncthreads();
        for (int off = 1; off < 1024; off <<= 1) {
            int t = (tid >= off) ? sh[tid - off] : 0;
            __syncthreads();
            sh[tid] += t;
            __syncthreads();
        }
        int inc = sh[tid] + carry;
        if (i < N_NODES) { g_rowptr[i + 1] = inc; g_cursor[i] = inc - v; }
        __syncthreads();
        if (tid == 1023) carry = inc;
        __syncthreads();
    }
}
__global__ void scatter_kernel(const int* __restrict__ ei0, const int* __restrict__ ei1) {
    int i = blockIdx.x * blockDim.x + threadIdx.x;
    if (i >= 2 * E_EDGES) return;
    int r = (i < E_EDGES) ? 0 : 1;
    int e = r ? (i - E_EDGES) : i;
    const int* ei = r ? ei1 : ei0;
    int src = ei[e];
    int dst = ei[E_EDGES + e];
    int pos = atomicAdd(&g_cursor[dst], 1);
    g_eadj[pos] = (src << 1) | r;
}

// ===================== mma.sync bf16-split GEMM ==============================
// C[M x Nn] = (Ahi+Alo)[M x 256] @ (Bhi+Blo)^T  with B stored [n][k].
// CTA 128x128, 8 warps (2x4), warp tile 64x32, BK=64, cp.async double buffer.
#define BK 64
#define SROW 72                       // padded row length (elements)
#define SROWB 144                     // bytes
#define TILE_B (128 * SROWB)          // 18432 B per matrix per stage
#define STAGE_B (4 * TILE_B)          // Ah, Al, Bh, Bl
#define GEMM_SMEM (2 * STAGE_B)       // 147456

struct GemmPtrs {
    const __nv_bfloat16 *Ah, *Al, *Bh, *Bl;
};

__device__ __forceinline__ void load_stage(
    uint32_t smb, int buf, const GemmPtrs& p, int m0, int n0, int k0,
    int M, int tid)
{
    const uint32_t base = smb + buf * STAGE_B;
    const int c = tid & 7;           // 16B column within 128B of data
    const int r0 = tid >> 3;         // 0..31
#pragma unroll
    for (int q = 0; q < 4; q++) {
        int row = r0 + q * 32;
        uint32_t doff = (uint32_t)row * SROWB + c * 16;
        // A rows may exceed M
        int grow = m0 + row;
        int va = (grow < M) ? 16 : 0;
        size_t aoff = ((size_t)(va ? grow : 0) * KTOT + k0) * 2 + c * 16;
        cpasync16(base + doff,              (const char*)p.Ah + aoff, va);
        cpasync16(base + TILE_B + doff,     (const char*)p.Al + aoff, va);
        size_t boff = ((size_t)(n0 + row) * KTOT + k0) * 2 + c * 16;
        cpasync16(base + 2 * TILE_B + doff, (const char*)p.Bh + boff, 16);
        cpasync16(base + 3 * TILE_B + doff, (const char*)p.Bl + boff, 16);
    }
    asm volatile("cp.async.commit_group;" ::: "memory");
}

__global__ __launch_bounds__(256, 1) void gemm_tc(
    const __nv_bfloat16* __restrict__ Ahi, const __nv_bfloat16* __restrict__ Alo,
    const __nv_bfloat16* __restrict__ Bhi, const __nv_bfloat16* __restrict__ Blo,
    const float* __restrict__ bias, float* __restrict__ C,
    int M, int Nn,
    const float* __restrict__ prev, const float* __restrict__ skipp)
{
    extern __shared__ char sm[];
    const uint32_t smb = smem_u32(sm);
    const int tid = threadIdx.x;
    const int wid = tid >> 5;
    const int lane = tid & 31;
    const int wrow = wid & 1;        // 2 warp-rows of 64
    const int wcol = wid >> 1;       // 4 warp-cols of 32
    const int m0 = blockIdx.y * 128;
    const int n0 = blockIdx.x * 128;

    GemmPtrs p{Ahi, Alo, Bhi, Blo};

    float acc[4][4][4];              // [m16 block][n8 block][c0..c3]
#pragma unroll
    for (int i = 0; i < 4; i++)
#pragma unroll
        for (int j = 0; j < 4; j++)
#pragma unroll
            for (int q = 0; q < 4; q++) acc[i][j][q] = 0.f;

    // ldmatrix lane addressing
    const int a_row = lane & 15;
    const int a_k8  = (lane >> 4) * 8;
    const int b_row = (lane & 7) | ((lane >> 4) << 3);
    const int b_k8  = ((lane >> 3) & 1) * 8;

    load_stage(smb, 0, p, m0, n0, 0, M, tid);

#pragma unroll
    for (int s = 0; s < 4; s++) {
        if (s < 3) load_stage(smb, (s + 1) & 1, p, m0, n0, (s + 1) * BK, M, tid);
        if (s < 3) asm volatile("cp.async.wait_group 1;" ::: "memory");
        else       asm volatile("cp.async.wait_group 0;" ::: "memory");
        __syncthreads();

        const uint32_t base = smb + (s & 1) * STAGE_B;
        const uint32_t aB = base + (uint32_t)(wrow * 64 + a_row) * SROWB + a_k8 * 2;
        const uint32_t bB = base + 2 * TILE_B + (uint32_t)(wcol * 32 + b_row) * SROWB + b_k8 * 2;

#pragma unroll
        for (int kk = 0; kk < BK / 16; kk++) {
            uint32_t Ah[4][4], Al[4][4];
#pragma unroll
            for (int mb = 0; mb < 4; mb++) {
                uint32_t ad = aB + (uint32_t)mb * 16 * SROWB + kk * 32;
                ldm_x4(Ah[mb], ad);
                ldm_x4(Al[mb], ad + TILE_B);
            }
            uint32_t Bh[2][4], Bl[2][4];
#pragma unroll
            for (int nl = 0; nl < 2; nl++) {
                uint32_t bd = bB + (uint32_t)nl * 16 * SROWB + kk * 32;
                ldm_x4(Bh[nl], bd);
                ldm_x4(Bl[nl], bd + TILE_B);
            }
#pragma unroll
            for (int mb = 0; mb < 4; mb++) {
#pragma unroll
                for (int nb = 0; nb < 4; nb++) {
                    const uint32_t* bh = &Bh[nb >> 1][(nb & 1) * 2];
                    const uint32_t* bl = &Bl[nb >> 1][(nb & 1) * 2];
                    mma_bf16(acc[mb][nb], Ah[mb], bh);
                    mma_bf16(acc[mb][nb], Ah[mb], bl);
                    mma_bf16(acc[mb][nb], Al[mb], bh);
                }
            }
        }
        __syncthreads();
    }

    // epilogue
    float sc = 1.f, om = 0.f;
    if (skipp) { float sk = *skipp; sc = 1.f / (1.f + __expf(-sk)); om = 1.f - sc; }

    const int lr = lane >> 2;        // row within 8
    const int lc = (lane & 3) * 2;   // col pair
#pragma unroll
    for (int mb = 0; mb < 4; mb++) {
#pragma unroll
        for (int half = 0; half < 2; half++) {
            int grow = m0 + wrow * 64 + mb * 16 + lr + half * 8;
            if (grow >= M) continue;
#pragma unroll
            for (int nb = 0; nb < 4; nb++) {
                int gcol = n0 + wcol * 32 + nb * 8 + lc;
                float v0 = acc[mb][nb][half * 2 + 0] + bias[gcol];
                float v1 = acc[mb][nb][half * 2 + 1] + bias[gcol + 1];
                if (prev) {
                    const float2 pv = *(const float2*)(prev + (size_t)grow * Nn + gcol);
                    v0 = sc * v0 + om * pv.x;
                    v1 = sc * v1 + om * pv.y;
                }
                *(float2*)(C + (size_t)grow * Nn + gcol) = make_float2(v0, v1);
            }
        }
    }
}

// ================ edge aggregation: warp per dst, online softmax ============
__global__ __launch_bounds__(256) void edge_agg(const float* __restrict__ prel_l) {
    int warp = (blockIdx.x * blockDim.x + threadIdx.x) >> 5;
    int lane = threadIdx.x & 31;
    if (warp >= N_NODES) return;
    const int n = warp;
    const int h = lane >> 2;
    const int q8 = (lane & 3) * 8;

    const float* qp = g_P + (long)n * PCOLS + h * DHEAD + q8;
    float4 q0 = *(const float4*)qp;
    float4 q1 = *(const float4*)(qp + 4);
    const float scale = 0.17677669529663687f;  // 1/sqrt(32)
    const float p0 = prel_l[h] * scale;
    const float p1 = prel_l[HHEADS + h] * scale;

    float m = -INFINITY, ssum = 0.f;
    float acc[8];
#pragma unroll
    for (int i = 0; i < 8; i++) acc[i] = 0.f;

    const int e0 = g_rowptr[n], e1 = g_rowptr[n + 1];
    for (int e = e0; e < e1; e++) {
        int pk = g_eadj[e];
        int r = pk & 1;
        int src = pk >> 1;
        const float* base = g_P + (long)src * PCOLS;
        const float* kp = base + CDIM + r * CDIM + h * DHEAD + q8;
        const float* vp = base + 3 * CDIM + r * CDIM + h * DHEAD + q8;
        float4 k0 = *(const float4*)kp;
        float4 k1 = *(const float4*)(kp + 4);
        float4 v0 = *(const float4*)vp;
        float4 v1 = *(const float4*)(vp + 4);
        float d = q0.x * k0.x + q0.y * k0.y + q0.z * k0.z + q0.w * k0.w
                + q1.x * k1.x + q1.y * k1.y + q1.z * k1.z + q1.w * k1.w;
        d += __shfl_xor_sync(0xffffffffu, d, 1);
        d += __shfl_xor_sync(0xffffffffu, d, 2);
        float lg = d * (r ? p1 : p0);
        float nm = fmaxf(m, lg);
        float cf = __expf(m - nm);
        float pw = __expf(lg - nm);
        ssum = ssum * cf + pw;
        m = nm;
        acc[0] = acc[0] * cf + pw * v0.x;
        acc[1] = acc[1] * cf + pw * v0.y;
        acc[2] = acc[2] * cf + pw * v0.z;
        acc[3] = acc[3] * cf + pw * v0.w;
        acc[4] = acc[4] * cf + pw * v1.x;
        acc[5] = acc[5] * cf + pw * v1.y;
        acc[6] = acc[6] * cf + pw * v1.z;
        acc[7] = acc[7] * cf + pw * v1.w;
    }

    float inv = 1.0f / fmaxf(ssum, 1e-16f);
    float out[8];
#pragma unroll
    for (int i = 0; i < 8; i++) {
        float xg = acc[i] * inv;
        out[i] = 0.5f * xg * (1.0f + erff(xg * 0.70710678118654752f));
    }
    float* gp = g_G + (long)n * CDIM + h * DHEAD + q8;
    *(float4*)gp       = make_float4(out[0], out[1], out[2], out[3]);
    *(float4*)(gp + 4) = make_float4(out[4], out[5], out[6], out[7]);
}

// ================ fused relu + layernorm ====================================
__global__ __launch_bounds__(256) void relu_ln(float* __restrict__ hbuf,
                                               const float* __restrict__ g,
                                               const float* __restrict__ b) {
    int warp = (blockIdx.x * blockDim.x + threadIdx.x) >> 5;
    int lane = threadIdx.x & 31;
    if (warp >= N_NODES) return;
    float* row = hbuf + (long)warp * CDIM;
    float v[8];
    *(float4*)(v)     = *(const float4*)(row + lane * 8);
    *(float4*)(v + 4) = *(const float4*)(row + lane * 8 + 4);
    float s = 0.f, s2 = 0.f;
#pragma unroll
    for (int i = 0; i < 8; i++) {
        v[i] = fmaxf(v[i], 0.f);
        s += v[i];
        s2 += v[i] * v[i];
    }
#pragma unroll
    for (int off = 16; off > 0; off >>= 1) {
        s += __shfl_xor_sync(0xffffffffu, s, off);
        s2 += __shfl_xor_sync(0xffffffffu, s2, off);
    }
    float mu = s * (1.f / CDIM);
    float var = s2 * (1.f / CDIM) - mu * mu;
    float rs = rsqrtf(var + 1e-5f);
#pragma unroll
    for (int i = 0; i < 8; i++) {
        int c = lane * 8 + i;
        v[i] = (v[i] - mu) * rs * g[c] + b[c];
    }
    *(float4*)(row + lane * 8)     = *(const float4*)(v);
    *(float4*)(row + lane * 8 + 4) = *(const float4*)(v + 4);
}

// ===================== launch ================================================
extern "C" void kernel_launch(void* const* d_in, const int* in_sizes, int n_in,
                              void* d_out, int out_size) {
    const float* x      = (const float*)d_in[0];
    const int*   ei0    = (const int*)d_in[1];
    const int*   ei1    = (const int*)d_in[2];
    const float* kqv_w  = (const float*)d_in[3];
    const float* kqv_b  = (const float*)d_in[4];
    const float* out_w  = (const float*)d_in[5];
    const float* out_b  = (const float*)d_in[6];
    const float* skip   = (const float*)d_in[7];
    const float* krel   = (const float*)d_in[8];
    const float* vrel   = (const float*)d_in[9];
    const float* prel   = (const float*)d_in[10];
    const float* ln_g   = (const float*)d_in[11];
    const float* ln_b   = (const float*)d_in[12];
    float* out = (float*)d_out;

    cudaFuncSetAttribute(gemm_tc, cudaFuncAttributeMaxDynamicSharedMemorySize, GEMM_SMEM);

    float *hA, *hB, *bf, *P, *G;
    __nv_bfloat16 *W1h, *W1l, *W2h, *W2l, *Ah, *Al;
    cudaGetSymbolAddress((void**)&hA, g_hA);
    cudaGetSymbolAddress((void**)&hB, g_hB);
    cudaGetSymbolAddress((void**)&bf, g_bfv);
    cudaGetSymbolAddress((void**)&P, g_P);
    cudaGetSymbolAddress((void**)&G, g_G);
    cudaGetSymbolAddress((void**)&W1h, g_W1hi);
    cudaGetSymbolAddress((void**)&W1l, g_W1lo);
    cudaGetSymbolAddress((void**)&W2h, g_W2hi);
    cudaGetSymbolAddress((void**)&W2l, g_W2lo);
    cudaGetSymbolAddress((void**)&Ah, g_Ahi);
    cudaGetSymbolAddress((void**)&Al, g_Alo);

    // ---- preprocess (weights + CSR) ----
    {
        long t1 = (long)L_LAYERS * CDIM * PCOLS;
        fold_w1<<<(int)((t1 + 255) / 256), 256>>>(kqv_w, krel, vrel);
        long t2 = (long)L_LAYERS * CDIM * CDIM;
        fold_w2<<<(int)((t2 + 255) / 256), 256>>>(out_w);
        fold_bias<<<(L_LAYERS * PCOLS + 255) / 256, 256>>>(kqv_b, krel, vrel);
        zero_deg<<<(N_NODES + 255) / 256, 256>>>();
        hist_kernel<<<(2 * E_EDGES + 255) / 256, 256>>>(ei0, ei1);
        scan_kernel<<<1, 1024>>>();
        scatter_kernel<<<(2 * E_EDGES + 255) / 256, 256>>>(ei0, ei1);
    }

    const int n4 = N_NODES * CDIM / 4;
    const int MT = (N_NODES + 127) / 128;  // 157
    const float* hin = x;

    for (int l = 0; l < L_LAYERS; l++) {
        float* hout = (l == 3) ? out : ((l % 2 == 0) ? hA : hB);

        // split hin -> bf16 hi/lo
        split_fp32<<<(n4 + 255) / 256, 256>>>(hin, n4);

        // GEMM1: P = hin @ W1^T + bias  [N,1280]
        gemm_tc<<<dim3(PCOLS / 128, MT), 256, GEMM_SMEM>>>(
            Ah, Al, W1h + (size_t)l * PCOLS * CDIM, W1l + (size_t)l * PCOLS * CDIM,
            bf + (size_t)l * PCOLS, P, N_NODES, PCOLS, nullptr, nullptr);

        // edge aggregation + softmax + gelu -> g_G
        edge_agg<<<(N_NODES * 32) / 256, 256>>>(prel + (size_t)l * R_REL * HHEADS);

        // split G -> bf16 hi/lo
        split_fp32<<<(n4 + 255) / 256, 256>>>(G, n4);

        // GEMM2: hout = s*(G @ W2^T + out_b) + (1-s)*hin
        gemm_tc<<<dim3(CDIM / 128, MT), 256, GEMM_SMEM>>>(
            Ah, Al, W2h + (size_t)l * CDIM * CDIM, W2l + (size_t)l * CDIM * CDIM,
            out_b + (size_t)l * CDIM, hout, N_NODES, CDIM, hin, skip + l);

        if (l < L_LAYERS - 1) {
            relu_ln<<<(N_NODES * 32) / 256, 256>>>(hout, ln_g + (size_t)l * CDIM,
                                                   ln_b + (size_t)l * CDIM);
        }
        hin = hout;
    }
}

// round 4
// speedup vs baseline: 2.3629x; 1.3131x over previous
#include <cuda_runtime.h>
#include <cuda_bf16.h>
#include <math.h>
#include <stdint.h>

#define N_NODES 20000
#define CDIM 256
#define HHEADS 8
#define DHEAD 32
#define E_EDGES 160000
#define L_LAYERS 4
#define R_REL 2
#define PCOLS 1280   // q(256) | k_r0(256) | k_r1(256) | v_r0(256) | v_r1(256)
#define KTOT 256

// ===================== scratch (device globals) =============================
__device__ float g_Q[(size_t)N_NODES * CDIM];                      // q fp32
__device__ __nv_bfloat16 g_KV[(size_t)N_NODES * 1024];             // [n][r][k256|v256]
__device__ float g_hA[(size_t)N_NODES * CDIM];
__device__ float g_hB[(size_t)N_NODES * CDIM];
__device__ float g_bfv[(size_t)L_LAYERS * PCOLS];
__device__ __nv_bfloat16 g_W1hi[(size_t)L_LAYERS * PCOLS * CDIM];  // [l][n][k]
__device__ __nv_bfloat16 g_W1lo[(size_t)L_LAYERS * PCOLS * CDIM];
__device__ __nv_bfloat16 g_W2hi[(size_t)L_LAYERS * CDIM * CDIM];   // [l][n][k]
__device__ __nv_bfloat16 g_W2lo[(size_t)L_LAYERS * CDIM * CDIM];
__device__ __nv_bfloat16 g_Ahi[(size_t)N_NODES * CDIM];
__device__ __nv_bfloat16 g_Alo[(size_t)N_NODES * CDIM];
__device__ int g_deg[N_NODES];
__device__ int g_rowptr[N_NODES + 1];
__device__ int g_cursor[N_NODES];
__device__ int g_eadj[2 * E_EDGES];

// ===================== small PTX helpers ====================================
__device__ __forceinline__ uint32_t smem_u32(const void* p) {
    uint32_t a;
    asm("{ .reg .u64 t; cvta.to.shared.u64 t, %1; cvt.u32.u64 %0, t; }"
        : "=r"(a) : "l"(p));
    return a;
}
__device__ __forceinline__ void cpasync16(uint32_t dst, const void* src, int src_sz) {
    asm volatile("cp.async.cg.shared.global [%0], [%1], 16, %2;"
                 :: "r"(dst), "l"(src), "r"(src_sz));
}
__device__ __forceinline__ void ldm_x4(uint32_t* r, uint32_t addr) {
    asm volatile("ldmatrix.sync.aligned.m8n8.x4.shared.b16 {%0,%1,%2,%3}, [%4];"
                 : "=r"(r[0]), "=r"(r[1]), "=r"(r[2]), "=r"(r[3]) : "r"(addr));
}
__device__ __forceinline__ void mma_bf16(float* c, const uint32_t* a, const uint32_t* b) {
    asm volatile("mma.sync.aligned.m16n8k16.row.col.f32.bf16.bf16.f32 "
                 "{%0,%1,%2,%3}, {%4,%5,%6,%7}, {%8,%9}, {%0,%1,%2,%3};"
                 : "+f"(c[0]), "+f"(c[1]), "+f"(c[2]), "+f"(c[3])
                 : "r"(a[0]), "r"(a[1]), "r"(a[2]), "r"(a[3]),
                   "r"(b[0]), "r"(b[1]));
}

// ===================== fused preprocess (fat kernel) =========================
// blocks: [0,1250) hist | [1250,6370) fold_w1 | [6370,7394) fold_w2
//         [7394,7414) fold_bias | [7414,12414) split_x
#define NB_HIST 1250
#define NB_FW1 5120
#define NB_FW2 1024
#define NB_FB 20
#define NB_SPLIT 5000
#define NB_TOTAL (NB_HIST + NB_FW1 + NB_FW2 + NB_FB + NB_SPLIT)

__device__ __forceinline__ void do_fold_w1(long idx, const float* kqv_w,
                                           const float* krel, const float* vrel) {
    int j = (int)(idx % PCOLS);
    int c = (int)((idx / PCOLS) % CDIM);
    int l = (int)(idx / ((long)PCOLS * CDIM));
    const float* W = kqv_w + ((long)l * CDIM + c) * (3 * CDIM);
    float val;
    if (j < CDIM) {
        val = W[CDIM + j];  // q (split order k,q,v)
    } else {
        int jj = j - CDIM;
        int sec = jj >> 8;
        int r = sec & 1;
        int isv = sec >> 1;
        int hf = jj & 255;
        int h = hf >> 5, f = hf & 31;
        const float* M = (isv ? vrel : krel) +
                         ((((long)l * R_REL + r) * HHEADS + h) * DHEAD) * DHEAD + f;
        const float* wk = W + (isv ? 2 * CDIM : 0) + h * DHEAD;
        float s = 0.f;
#pragma unroll
        for (int d = 0; d < DHEAD; d++) s += wk[d] * M[(long)d * DHEAD];
        val = s;
    }
    __nv_bfloat16 hi = __float2bfloat16(val);
    __nv_bfloat16 lo = __float2bfloat16(val - __bfloat162float(hi));
    long o = ((long)l * PCOLS + j) * CDIM + c;
    g_W1hi[o] = hi;
    g_W1lo[o] = lo;
}

__global__ __launch_bounds__(256) void fat_pre(
    const int* __restrict__ ei0, const int* __restrict__ ei1,
    const float* __restrict__ kqv_w, const float* __restrict__ kqv_b,
    const float* __restrict__ out_w,
    const float* __restrict__ krel, const float* __restrict__ vrel,
    const float* __restrict__ x)
{
    int bx = blockIdx.x;
    if (bx < NB_HIST) {
        int i = bx * 256 + threadIdx.x;
        if (i < 2 * E_EDGES) {
            int dst = (i < E_EDGES) ? ei0[E_EDGES + i] : ei1[E_EDGES + (i - E_EDGES)];
            atomicAdd(&g_deg[dst], 1);
        }
        return;
    }
    bx -= NB_HIST;
    if (bx < NB_FW1) {
        long idx = (long)bx * 256 + threadIdx.x;
        do_fold_w1(idx, kqv_w, krel, vrel);
        return;
    }
    bx -= NB_FW1;
    if (bx < NB_FW2) {
        long idx = (long)bx * 256 + threadIdx.x;
        int n = (int)(idx & 255);
        int k = (int)((idx >> 8) & 255);
        int l = (int)(idx >> 16);
        float val = out_w[((long)l * CDIM + k) * CDIM + n];
        __nv_bfloat16 hi = __float2bfloat16(val);
        __nv_bfloat16 lo = __float2bfloat16(val - __bfloat162float(hi));
        long o = ((long)l * CDIM + n) * CDIM + k;
        g_W2hi[o] = hi;
        g_W2lo[o] = lo;
        return;
    }
    bx -= NB_FW2;
    if (bx < NB_FB) {
        int idx = bx * 256 + threadIdx.x;
        if (idx < L_LAYERS * PCOLS) {
            int j = idx % PCOLS;
            int l = idx / PCOLS;
            const float* b = kqv_b + (long)l * 3 * CDIM;
            float val;
            if (j < CDIM) {
                val = b[CDIM + j];
            } else {
                int jj = j - CDIM;
                int sec = jj >> 8;
                int r = sec & 1;
                int isv = sec >> 1;
                int hf = jj & 255;
                int h = hf >> 5, f = hf & 31;
                const float* M = (isv ? vrel : krel) +
                                 ((((long)l * R_REL + r) * HHEADS + h) * DHEAD) * DHEAD + f;
                const float* bk = b + (isv ? 2 * CDIM : 0) + h * DHEAD;
                float s = 0.f;
#pragma unroll
                for (int d = 0; d < DHEAD; d++) s += bk[d] * M[(long)d * DHEAD];
                val = s;
            }
            g_bfv[idx] = val;
        }
        return;
    }
    bx -= NB_FB;
    {   // split x -> Ahi/Alo
        int i = bx * 256 + threadIdx.x;
        if (i < N_NODES * CDIM / 4) {
            float4 v = ((const float4*)x)[i];
            __nv_bfloat16 h0 = __float2bfloat16(v.x), h1 = __float2bfloat16(v.y);
            __nv_bfloat16 h2 = __float2bfloat16(v.z), h3 = __float2bfloat16(v.w);
            __nv_bfloat162 hi01; hi01.x = h0; hi01.y = h1;
            __nv_bfloat162 hi23; hi23.x = h2; hi23.y = h3;
            __nv_bfloat162 lo01, lo23;
            lo01.x = __float2bfloat16(v.x - __bfloat162float(h0));
            lo01.y = __float2bfloat16(v.y - __bfloat162float(h1));
            lo23.x = __float2bfloat16(v.z - __bfloat162float(h2));
            lo23.y = __float2bfloat16(v.w - __bfloat162float(h3));
            ((__nv_bfloat162*)g_Ahi)[i * 2]     = hi01;
            ((__nv_bfloat162*)g_Ahi)[i * 2 + 1] = hi23;
            ((__nv_bfloat162*)g_Alo)[i * 2]     = lo01;
            ((__nv_bfloat162*)g_Alo)[i * 2 + 1] = lo23;
        }
    }
}

// ===================== scan (also re-zeroes g_deg for graph replay) =========
__global__ void scan_kernel() {
    __shared__ int sh[1024];
    __shared__ int carry;
    int tid = threadIdx.x;
    if (tid == 0) { carry = 0; g_rowptr[0] = 0; }
    __syncthreads();
    for (int base = 0; base < N_NODES; base += 1024) {
        int i = base + tid;
        int v = (i < N_NODES) ? g_deg[i] : 0;
        if (i < N_NODES) g_deg[i] = 0;   // ready for next replay
        sh[tid] = v;
        __syncthreads();
        for (int off = 1; off < 1024; off <<= 1) {
            int t = (tid >= off) ? sh[tid - off] : 0;
            __syncthreads();
            sh[tid] += t;
            __syncthreads();
        }
        int inc = sh[tid] + carry;
        if (i < N_NODES) { g_rowptr[i + 1] = inc; g_cursor[i] = inc - v; }
        __syncthreads();
        if (tid == 1023) carry = inc;
        __syncthreads();
    }
}

__global__ void scatter_kernel(const int* __restrict__ ei0, const int* __restrict__ ei1) {
    int i = blockIdx.x * blockDim.x + threadIdx.x;
    if (i >= 2 * E_EDGES) return;
    int r = (i < E_EDGES) ? 0 : 1;
    int e = r ? (i - E_EDGES) : i;
    const int* ei = r ? ei1 : ei0;
    int src = ei[e];
    int dst = ei[E_EDGES + e];
    int pos = atomicAdd(&g_cursor[dst], 1);
    g_eadj[pos] = (src << 1) | r;
}

// ===================== mma.sync bf16-split GEMM ==============================
// CTA 128x128, 8 warps (2x4), warp tile 64x32, BK=64, cp.async double buffer.
// Tiles with n0 <  n_full3 : 3-term split (Ah·Bh + Ah·Bl + Al·Bh)
// Tiles with n0 >= n_full3 : 1-term (Ah·Bh)  [bf16-precision outputs]
// mode 0: proj epilogue -> qOut fp32 (cols<256) / kvOut bf16 (cols>=256)
// mode 1: out epilogue  -> Cout fp32 with bias + sigmoid-skip blend vs prev
#define BK 64
#define SROWB 144
#define TILE_B (128 * SROWB)
#define STAGE_B (4 * TILE_B)
#define GEMM_SMEM (2 * STAGE_B)

struct GemmPtrs {
    const __nv_bfloat16 *Ah, *Al, *Bh, *Bl;
};

__device__ __forceinline__ void load_stage(
    uint32_t smb, int buf, const GemmPtrs& p, int m0, int n0, int k0,
    int M, int tid, bool full)
{
    const uint32_t base = smb + buf * STAGE_B;
    const int c = tid & 7;
    const int r0 = tid >> 3;
#pragma unroll
    for (int q = 0; q < 4; q++) {
        int row = r0 + q * 32;
        uint32_t doff = (uint32_t)row * SROWB + c * 16;
        int grow = m0 + row;
        int va = (grow < M) ? 16 : 0;
        size_t aoff = ((size_t)(va ? grow : 0) * KTOT + k0) * 2 + c * 16;
        cpasync16(base + doff, (const char*)p.Ah + aoff, va);
        size_t boff = ((size_t)(n0 + row) * KTOT + k0) * 2 + c * 16;
        cpasync16(base + 2 * TILE_B + doff, (const char*)p.Bh + boff, 16);
        if (full) {
            cpasync16(base + TILE_B + doff,     (const char*)p.Al + aoff, va);
            cpasync16(base + 3 * TILE_B + doff, (const char*)p.Bl + boff, 16);
        }
    }
    asm volatile("cp.async.commit_group;" ::: "memory");
}

__global__ __launch_bounds__(256, 1) void gemm_tc(
    const __nv_bfloat16* __restrict__ Ahi, const __nv_bfloat16* __restrict__ Alo,
    const __nv_bfloat16* __restrict__ Bhi, const __nv_bfloat16* __restrict__ Blo,
    const float* __restrict__ bias,
    int M, int Nn, int n_full3, int mode,
    float* __restrict__ Cout, const float* __restrict__ prev,
    const float* __restrict__ skipp,
    float* __restrict__ qOut, __nv_bfloat16* __restrict__ kvOut)
{
    extern __shared__ char sm[];
    const uint32_t smb = smem_u32(sm);
    const int tid = threadIdx.x;
    const int wid = tid >> 5;
    const int lane = tid & 31;
    const int wrow = wid & 1;
    const int wcol = wid >> 1;
    const int m0 = blockIdx.y * 128;
    const int n0 = blockIdx.x * 128;
    const bool full = (n0 < n_full3);

    GemmPtrs p{Ahi, Alo, Bhi, Blo};

    float acc[4][4][4];
#pragma unroll
    for (int i = 0; i < 4; i++)
#pragma unroll
        for (int j = 0; j < 4; j++)
#pragma unroll
            for (int q = 0; q < 4; q++) acc[i][j][q] = 0.f;

    const int a_row = lane & 15;
    const int a_k8  = (lane >> 4) * 8;
    const int b_row = (lane & 7) | ((lane >> 4) << 3);
    const int b_k8  = ((lane >> 3) & 1) * 8;

    load_stage(smb, 0, p, m0, n0, 0, M, tid, full);

#pragma unroll
    for (int s = 0; s < 4; s++) {
        if (s < 3) load_stage(smb, (s + 1) & 1, p, m0, n0, (s + 1) * BK, M, tid, full);
        if (s < 3) asm volatile("cp.async.wait_group 1;" ::: "memory");
        else       asm volatile("cp.async.wait_group 0;" ::: "memory");
        __syncthreads();

        const uint32_t base = smb + (s & 1) * STAGE_B;
        const uint32_t aB = base + (uint32_t)(wrow * 64 + a_row) * SROWB + a_k8 * 2;
        const uint32_t bB = base + 2 * TILE_B + (uint32_t)(wcol * 32 + b_row) * SROWB + b_k8 * 2;

        if (full) {
#pragma unroll
            for (int kk = 0; kk < BK / 16; kk++) {
                uint32_t Ah[4][4], Al[4][4];
#pragma unroll
                for (int mb = 0; mb < 4; mb++) {
                    uint32_t ad = aB + (uint32_t)mb * 16 * SROWB + kk * 32;
                    ldm_x4(Ah[mb], ad);
                    ldm_x4(Al[mb], ad + TILE_B);
                }
                uint32_t Bh[2][4], Bl[2][4];
#pragma unroll
                for (int nl = 0; nl < 2; nl++) {
                    uint32_t bd = bB + (uint32_t)nl * 16 * SROWB + kk * 32;
                    ldm_x4(Bh[nl], bd);
                    ldm_x4(Bl[nl], bd + TILE_B);
                }
#pragma unroll
                for (int mb = 0; mb < 4; mb++) {
#pragma unroll
                    for (int nb = 0; nb < 4; nb++) {
                        const uint32_t* bh = &Bh[nb >> 1][(nb & 1) * 2];
                        const uint32_t* bl = &Bl[nb >> 1][(nb & 1) * 2];
                        mma_bf16(acc[mb][nb], Ah[mb], bh);
                        mma_bf16(acc[mb][nb], Ah[mb], bl);
                        mma_bf16(acc[mb][nb], Al[mb], bh);
                    }
                }
            }
        } else {
#pragma unroll
            for (int kk = 0; kk < BK / 16; kk++) {
                uint32_t Ah[4][4];
#pragma unroll
                for (int mb = 0; mb < 4; mb++)
                    ldm_x4(Ah[mb], aB + (uint32_t)mb * 16 * SROWB + kk * 32);
                uint32_t Bh[2][4];
#pragma unroll
                for (int nl = 0; nl < 2; nl++)
                    ldm_x4(Bh[nl], bB + (uint32_t)nl * 16 * SROWB + kk * 32);
#pragma unroll
                for (int mb = 0; mb < 4; mb++)
#pragma unroll
                    for (int nb = 0; nb < 4; nb++)
                        mma_bf16(acc[mb][nb], Ah[mb], &Bh[nb >> 1][(nb & 1) * 2]);
            }
        }
        __syncthreads();
    }

    // ---- epilogue ----
    float sc = 1.f, om = 0.f;
    if (mode == 1) { float sk = *skipp; sc = 1.f / (1.f + __expf(-sk)); om = 1.f - sc; }

    const int lr = lane >> 2;
    const int lc = (lane & 3) * 2;
#pragma unroll
    for (int mb = 0; mb < 4; mb++) {
#pragma unroll
        for (int half = 0; half < 2; half++) {
            int grow = m0 + wrow * 64 + mb * 16 + lr + half * 8;
            if (grow >= M) continue;
#pragma unroll
            for (int nb = 0; nb < 4; nb++) {
                int gcol = n0 + wcol * 32 + nb * 8 + lc;
                float v0 = acc[mb][nb][half * 2 + 0] + bias[gcol];
                float v1 = acc[mb][nb][half * 2 + 1] + bias[gcol + 1];
                if (mode == 1) {
                    const float2 pv = *(const float2*)(prev + (size_t)grow * Nn + gcol);
                    v0 = sc * v0 + om * pv.x;
                    v1 = sc * v1 + om * pv.y;
                    *(float2*)(Cout + (size_t)grow * Nn + gcol) = make_float2(v0, v1);
                } else {
                    if (gcol < CDIM) {
                        *(float2*)(qOut + (size_t)grow * CDIM + gcol) = make_float2(v0, v1);
                    } else {
                        int t = gcol - CDIM;
                        int sec = t >> 8;               // 0,1: k r0/r1; 2,3: v r0/r1
                        int off = t & 255;
                        int dst = (sec & 1) * 512 + (sec >> 1) * 256 + off;
                        __nv_bfloat162 pk;
                        pk.x = __float2bfloat16(v0);
                        pk.y = __float2bfloat16(v1);
                        *(__nv_bfloat162*)(kvOut + (size_t)grow * 1024 + dst) = pk;
                    }
                }
            }
        }
    }
}

// ================ edge aggregation: warp per dst, online softmax ============
// KV bf16 gather (1KB/edge). Output: gelu(agg) split to bf16 hi/lo (GEMM2 A).
struct OState {
    float m, ssum;
    float acc[8];
};

__device__ __forceinline__ void edge_step(
    OState& st, uint4 kr, uint4 vr, float pr,
    const float* q)  // q[8]
{
    float2 k0 = __bfloat1622float2(*(__nv_bfloat162*)&kr.x);
    float2 k1 = __bfloat1622float2(*(__nv_bfloat162*)&kr.y);
    float2 k2 = __bfloat1622float2(*(__nv_bfloat162*)&kr.z);
    float2 k3 = __bfloat1622float2(*(__nv_bfloat162*)&kr.w);
    float d = q[0] * k0.x + q[1] * k0.y + q[2] * k1.x + q[3] * k1.y
            + q[4] * k2.x + q[5] * k2.y + q[6] * k3.x + q[7] * k3.y;
    d += __shfl_xor_sync(0xffffffffu, d, 1);
    d += __shfl_xor_sync(0xffffffffu, d, 2);
    float lg = d * pr;
    float nm = fmaxf(st.m, lg);
    float cf = __expf(st.m - nm);
    float pw = __expf(lg - nm);
    st.ssum = st.ssum * cf + pw;
    st.m = nm;
    float2 v0 = __bfloat1622float2(*(__nv_bfloat162*)&vr.x);
    float2 v1 = __bfloat1622float2(*(__nv_bfloat162*)&vr.y);
    float2 v2 = __bfloat1622float2(*(__nv_bfloat162*)&vr.z);
    float2 v3 = __bfloat1622float2(*(__nv_bfloat162*)&vr.w);
    st.acc[0] = st.acc[0] * cf + pw * v0.x;
    st.acc[1] = st.acc[1] * cf + pw * v0.y;
    st.acc[2] = st.acc[2] * cf + pw * v1.x;
    st.acc[3] = st.acc[3] * cf + pw * v1.y;
    st.acc[4] = st.acc[4] * cf + pw * v2.x;
    st.acc[5] = st.acc[5] * cf + pw * v2.y;
    st.acc[6] = st.acc[6] * cf + pw * v3.x;
    st.acc[7] = st.acc[7] * cf + pw * v3.y;
}

__global__ __launch_bounds__(256) void edge_agg(const float* __restrict__ prel_l) {
    int warp = (blockIdx.x * blockDim.x + threadIdx.x) >> 5;
    int lane = threadIdx.x & 31;
    if (warp >= N_NODES) return;
    const int n = warp;
    const int h = lane >> 2;
    const int d8 = (lane & 3) * 8;
    const int hoff = h * DHEAD + d8;

    float q[8];
    *(float4*)(q)     = *(const float4*)(g_Q + (size_t)n * CDIM + hoff);
    *(float4*)(q + 4) = *(const float4*)(g_Q + (size_t)n * CDIM + hoff + 4);
    const float scale = 0.17677669529663687f;  // 1/sqrt(32)
    const float p0 = prel_l[h] * scale;
    const float p1 = prel_l[HHEADS + h] * scale;

    OState st;
    st.m = -INFINITY; st.ssum = 0.f;
#pragma unroll
    for (int i = 0; i < 8; i++) st.acc[i] = 0.f;

    const int e0 = g_rowptr[n], e1 = g_rowptr[n + 1];
    int e = e0;
    for (; e + 2 <= e1; e += 2) {
        int pk0 = g_eadj[e];
        int pk1 = g_eadj[e + 1];
        const __nv_bfloat16* b0 = g_KV + ((size_t)(pk0 >> 1) * 1024 + (pk0 & 1) * 512 + hoff);
        const __nv_bfloat16* b1 = g_KV + ((size_t)(pk1 >> 1) * 1024 + (pk1 & 1) * 512 + hoff);
        uint4 k0 = __ldg((const uint4*)b0);
        uint4 v0 = __ldg((const uint4*)(b0 + 256));
        uint4 k1 = __ldg((const uint4*)b1);
        uint4 v1 = __ldg((const uint4*)(b1 + 256));
        edge_step(st, k0, v0, (pk0 & 1) ? p1 : p0, q);
        edge_step(st, k1, v1, (pk1 & 1) ? p1 : p0, q);
    }
    if (e < e1) {
        int pk = g_eadj[e];
        const __nv_bfloat16* b = g_KV + ((size_t)(pk >> 1) * 1024 + (pk & 1) * 512 + hoff);
        uint4 kr = __ldg((const uint4*)b);
        uint4 vr = __ldg((const uint4*)(b + 256));
        edge_step(st, kr, vr, (pk & 1) ? p1 : p0, q);
    }

    float inv = 1.0f / fmaxf(st.ssum, 1e-16f);
    uint4 uh, ul;
    __nv_bfloat162* ph = (__nv_bfloat162*)&uh;
    __nv_bfloat162* pl = (__nv_bfloat162*)&ul;
#pragma unroll
    for (int i = 0; i < 4; i++) {
        float x0 = st.acc[2 * i] * inv;
        float x1 = st.acc[2 * i + 1] * inv;
        float g0 = 0.5f * x0 * (1.0f + erff(x0 * 0.70710678118654752f));
        float g1 = 0.5f * x1 * (1.0f + erff(x1 * 0.70710678118654752f));
        __nv_bfloat16 h0 = __float2bfloat16(g0);
        __nv_bfloat16 h1 = __float2bfloat16(g1);
        ph[i].x = h0; ph[i].y = h1;
        pl[i].x = __float2bfloat16(g0 - __bfloat162float(h0));
        pl[i].y = __float2bfloat16(g1 - __bfloat162float(h1));
    }
    *(uint4*)(g_Ahi + (size_t)n * CDIM + hoff) = uh;
    *(uint4*)(g_Alo + (size_t)n * CDIM + hoff) = ul;
}

// ================ fused relu + layernorm + split ============================
__global__ __launch_bounds__(256) void relu_ln(float* __restrict__ hbuf,
                                               const float* __restrict__ g,
                                               const float* __restrict__ b) {
    int warp = (blockIdx.x * blockDim.x + threadIdx.x) >> 5;
    int lane = threadIdx.x & 31;
    if (warp >= N_NODES) return;
    float* row = hbuf + (size_t)warp * CDIM;
    float v[8];
    *(float4*)(v)     = *(const float4*)(row + lane * 8);
    *(float4*)(v + 4) = *(const float4*)(row + lane * 8 + 4);
    float s = 0.f, s2 = 0.f;
#pragma unroll
    for (int i = 0; i < 8; i++) {
        v[i] = fmaxf(v[i], 0.f);
        s += v[i];
        s2 += v[i] * v[i];
    }
#pragma unroll
    for (int off = 16; off > 0; off >>= 1) {
        s += __shfl_xor_sync(0xffffffffu, s, off);
        s2 += __shfl_xor_sync(0xffffffffu, s2, off);
    }
    float mu = s * (1.f / CDIM);
    float var = s2 * (1.f / CDIM) - mu * mu;
    float rs = rsqrtf(var + 1e-5f);
    uint4 uh, ul;
    __nv_bfloat162* ph = (__nv_bfloat162*)&uh;
    __nv_bfloat162* pl = (__nv_bfloat162*)&ul;
#pragma unroll
    for (int i = 0; i < 8; i++) {
        int c = lane * 8 + i;
        v[i] = (v[i] - mu) * rs * g[c] + b[c];
    }
#pragma unroll
    for (int i = 0; i < 4; i++) {
        __nv_bfloat16 h0 = __float2bfloat16(v[2 * i]);
        __nv_bfloat16 h1 = __float2bfloat16(v[2 * i + 1]);
        ph[i].x = h0; ph[i].y = h1;
        pl[i].x = __float2bfloat16(v[2 * i] - __bfloat162float(h0));
        pl[i].y = __float2bfloat16(v[2 * i + 1] - __bfloat162float(h1));
    }
    *(float4*)(row + lane * 8)     = *(const float4*)(v);
    *(float4*)(row + lane * 8 + 4) = *(const float4*)(v + 4);
    *(uint4*)(g_Ahi + (size_t)warp * CDIM + lane * 8) = uh;
    *(uint4*)(g_Alo + (size_t)warp * CDIM + lane * 8) = ul;
}

// ===================== launch ================================================
extern "C" void kernel_launch(void* const* d_in, const int* in_sizes, int n_in,
                              void* d_out, int out_size) {
    const float* x      = (const float*)d_in[0];
    const int*   ei0    = (const int*)d_in[1];
    const int*   ei1    = (const int*)d_in[2];
    const float* kqv_w  = (const float*)d_in[3];
    const float* kqv_b  = (const float*)d_in[4];
    const float* out_w  = (const float*)d_in[5];
    const float* out_b  = (const float*)d_in[6];
    const float* skip   = (const float*)d_in[7];
    const float* krel   = (const float*)d_in[8];
    const float* vrel   = (const float*)d_in[9];
    const float* prel   = (const float*)d_in[10];
    const float* ln_g   = (const float*)d_in[11];
    const float* ln_b   = (const float*)d_in[12];
    float* out = (float*)d_out;

    cudaFuncSetAttribute(gemm_tc, cudaFuncAttributeMaxDynamicSharedMemorySize, GEMM_SMEM);

    float *hA, *hB, *bf, *Q;
    __nv_bfloat16 *W1h, *W1l, *W2h, *W2l, *Ah, *Al, *KV;
    cudaGetSymbolAddress((void**)&hA, g_hA);
    cudaGetSymbolAddress((void**)&hB, g_hB);
    cudaGetSymbolAddress((void**)&bf, g_bfv);
    cudaGetSymbolAddress((void**)&Q, g_Q);
    cudaGetSymbolAddress((void**)&KV, g_KV);
    cudaGetSymbolAddress((void**)&W1h, g_W1hi);
    cudaGetSymbolAddress((void**)&W1l, g_W1lo);
    cudaGetSymbolAddress((void**)&W2h, g_W2hi);
    cudaGetSymbolAddress((void**)&W2l, g_W2lo);
    cudaGetSymbolAddress((void**)&Ah, g_Ahi);
    cudaGetSymbolAddress((void**)&Al, g_Alo);

    // preprocess: 3 launches, so launch #4 = gemm_tc (for ncu)
    fat_pre<<<NB_TOTAL, 256>>>(ei0, ei1, kqv_w, kqv_b, out_w, krel, vrel, x);
    scan_kernel<<<1, 1024>>>();
    scatter_kernel<<<(2 * E_EDGES + 255) / 256, 256>>>(ei0, ei1);

    const int MT = (N_NODES + 127) / 128;  // 157
    const float* hin = x;

    for (int l = 0; l < L_LAYERS; l++) {
        float* hout = (l == 3) ? out : ((l % 2 == 0) ? hA : hB);

        // GEMM1: [q fp32 | kv bf16] = A @ W1^T + bias
        gemm_tc<<<dim3(PCOLS / 128, MT), 256, GEMM_SMEM>>>(
            Ah, Al, W1h + (size_t)l * PCOLS * CDIM, W1l + (size_t)l * PCOLS * CDIM,
            bf + (size_t)l * PCOLS, N_NODES, PCOLS, /*n_full3=*/CDIM, /*mode=*/0,
            nullptr, nullptr, nullptr, Q, KV);

        // edge aggregation + softmax + gelu -> Ah/Al (bf16 split)
        edge_agg<<<(N_NODES * 32) / 256, 256>>>(prel + (size_t)l * R_REL * HHEADS);

        // GEMM2: hout = s*(G @ W2^T + out_b) + (1-s)*hin
        gemm_tc<<<dim3(CDIM / 128, MT), 256, GEMM_SMEM>>>(
            Ah, Al, W2h + (size_t)l * CDIM * CDIM, W2l + (size_t)l * CDIM * CDIM,
            out_b + (size_t)l * CDIM, N_NODES, CDIM, /*n_full3=*/CDIM, /*mode=*/1,
            hout, hin, skip + l, nullptr, nullptr);

        if (l < L_LAYERS - 1) {
            relu_ln<<<(N_NODES * 32) / 256, 256>>>(hout, ln_g + (size_t)l * CDIM,
                                                   ln_b + (size_t)l * CDIM);
        }
        hin = hout;
    }
}

// round 5
// speedup vs baseline: 2.9963x; 1.2680x over previous
#include <cuda_runtime.h>
#include <cuda_bf16.h>
#include <cuda_fp16.h>
#include <math.h>
#include <stdint.h>

#define N_NODES 20000
#define CDIM 256
#define HHEADS 8
#define DHEAD 32
#define E_EDGES 160000
#define L_LAYERS 4
#define R_REL 2
#define PCOLS 1280   // q(256) | k_r0(256) | k_r1(256) | v_r0(256) | v_r1(256)
#define KTOT 256

// ===================== scratch (device globals) =============================
__device__ float g_Q[(size_t)N_NODES * CDIM];                      // q fp32
__device__ __half g_KV[(size_t)N_NODES * 1024];                    // [n][r][k256|v256] fp16
__device__ float g_hA[(size_t)N_NODES * CDIM];
__device__ float g_hB[(size_t)N_NODES * CDIM];
__device__ float g_bfv[(size_t)L_LAYERS * PCOLS];
__device__ __half g_W1h[(size_t)L_LAYERS * PCOLS * CDIM];          // [l][n][k] fp16
__device__ __nv_bfloat16 g_W2hi[(size_t)L_LAYERS * CDIM * CDIM];   // [l][n][k]
__device__ __nv_bfloat16 g_W2lo[(size_t)L_LAYERS * CDIM * CDIM];
__device__ __half g_A16[(size_t)N_NODES * CDIM];                   // GEMM1 A (fp16)
__device__ __nv_bfloat16 g_Ahi[(size_t)N_NODES * CDIM];            // GEMM2 A hi
__device__ __nv_bfloat16 g_Alo[(size_t)N_NODES * CDIM];            // GEMM2 A lo
__device__ int g_deg[N_NODES];
__device__ int g_rowptr[N_NODES + 1];
__device__ int g_cursor[N_NODES];
__device__ int g_eadj[2 * E_EDGES];

// ===================== small PTX helpers ====================================
__device__ __forceinline__ uint32_t smem_u32(const void* p) {
    uint32_t a;
    asm("{ .reg .u64 t; cvta.to.shared.u64 t, %1; cvt.u32.u64 %0, t; }"
        : "=r"(a) : "l"(p));
    return a;
}
__device__ __forceinline__ void cpasync16(uint32_t dst, const void* src, int src_sz) {
    asm volatile("cp.async.cg.shared.global [%0], [%1], 16, %2;"
                 :: "r"(dst), "l"(src), "r"(src_sz));
}
__device__ __forceinline__ void ldm_x4(uint32_t* r, uint32_t addr) {
    asm volatile("ldmatrix.sync.aligned.m8n8.x4.shared.b16 {%0,%1,%2,%3}, [%4];"
                 : "=r"(r[0]), "=r"(r[1]), "=r"(r[2]), "=r"(r[3]) : "r"(addr));
}
__device__ __forceinline__ void mma_bf16(float* c, const uint32_t* a, const uint32_t* b) {
    asm volatile("mma.sync.aligned.m16n8k16.row.col.f32.bf16.bf16.f32 "
                 "{%0,%1,%2,%3}, {%4,%5,%6,%7}, {%8,%9}, {%0,%1,%2,%3};"
                 : "+f"(c[0]), "+f"(c[1]), "+f"(c[2]), "+f"(c[3])
                 : "r"(a[0]), "r"(a[1]), "r"(a[2]), "r"(a[3]),
                   "r"(b[0]), "r"(b[1]));
}
__device__ __forceinline__ void mma_f16(float* c, const uint32_t* a, const uint32_t* b) {
    asm volatile("mma.sync.aligned.m16n8k16.row.col.f32.f16.f16.f32 "
                 "{%0,%1,%2,%3}, {%4,%5,%6,%7}, {%8,%9}, {%0,%1,%2,%3};"
                 : "+f"(c[0]), "+f"(c[1]), "+f"(c[2]), "+f"(c[3])
                 : "r"(a[0]), "r"(a[1]), "r"(a[2]), "r"(a[3]),
                   "r"(b[0]), "r"(b[1]));
}

// ===================== fused preprocess (fat kernel) =========================
#define NB_HIST 1250
#define NB_FW1 5120
#define NB_FW2 1024
#define NB_FB 20
#define NB_SPLIT 5000
#define NB_TOTAL (NB_HIST + NB_FW1 + NB_FW2 + NB_FB + NB_SPLIT)

__device__ __forceinline__ float fold_w1_val(long idx, const float* kqv_w,
                                             const float* krel, const float* vrel) {
    int j = (int)(idx % PCOLS);
    int c = (int)((idx / PCOLS) % CDIM);
    int l = (int)(idx / ((long)PCOLS * CDIM));
    const float* W = kqv_w + ((long)l * CDIM + c) * (3 * CDIM);
    if (j < CDIM) return W[CDIM + j];  // q (split order k,q,v)
    int jj = j - CDIM;
    int sec = jj >> 8;
    int r = sec & 1;
    int isv = sec >> 1;
    int hf = jj & 255;
    int h = hf >> 5, f = hf & 31;
    const float* M = (isv ? vrel : krel) +
                     ((((long)l * R_REL + r) * HHEADS + h) * DHEAD) * DHEAD + f;
    const float* wk = W + (isv ? 2 * CDIM : 0) + h * DHEAD;
    float s = 0.f;
#pragma unroll
    for (int d = 0; d < DHEAD; d++) s += wk[d] * M[(long)d * DHEAD];
    return s;
}

__global__ __launch_bounds__(256) void fat_pre(
    const int* __restrict__ ei0, const int* __restrict__ ei1,
    const float* __restrict__ kqv_w, const float* __restrict__ kqv_b,
    const float* __restrict__ out_w,
    const float* __restrict__ krel, const float* __restrict__ vrel,
    const float* __restrict__ x)
{
    int bx = blockIdx.x;
    if (bx < NB_HIST) {
        int i = bx * 256 + threadIdx.x;
        if (i < 2 * E_EDGES) {
            int dst = (i < E_EDGES) ? ei0[E_EDGES + i] : ei1[E_EDGES + (i - E_EDGES)];
            atomicAdd(&g_deg[dst], 1);
        }
        return;
    }
    bx -= NB_HIST;
    if (bx < NB_FW1) {
        long idx = (long)bx * 256 + threadIdx.x;
        float val = fold_w1_val(idx, kqv_w, krel, vrel);
        int j = (int)(idx % PCOLS);
        int c = (int)((idx / PCOLS) % CDIM);
        int l = (int)(idx / ((long)PCOLS * CDIM));
        g_W1h[((long)l * PCOLS + j) * CDIM + c] = __float2half_rn(val);
        return;
    }
    bx -= NB_FW1;
    if (bx < NB_FW2) {
        long idx = (long)bx * 256 + threadIdx.x;
        int n = (int)(idx & 255);
        int k = (int)((idx >> 8) & 255);
        int l = (int)(idx >> 16);
        float val = out_w[((long)l * CDIM + k) * CDIM + n];
        __nv_bfloat16 hi = __float2bfloat16(val);
        __nv_bfloat16 lo = __float2bfloat16(val - __bfloat162float(hi));
        long o = ((long)l * CDIM + n) * CDIM + k;
        g_W2hi[o] = hi;
        g_W2lo[o] = lo;
        return;
    }
    bx -= NB_FW2;
    if (bx < NB_FB) {
        int idx = bx * 256 + threadIdx.x;
        if (idx < L_LAYERS * PCOLS) {
            int j = idx % PCOLS;
            int l = idx / PCOLS;
            const float* b = kqv_b + (long)l * 3 * CDIM;
            float val;
            if (j < CDIM) {
                val = b[CDIM + j];
            } else {
                int jj = j - CDIM;
                int sec = jj >> 8;
                int r = sec & 1;
                int isv = sec >> 1;
                int hf = jj & 255;
                int h = hf >> 5, f = hf & 31;
                const float* M = (isv ? vrel : krel) +
                                 ((((long)l * R_REL + r) * HHEADS + h) * DHEAD) * DHEAD + f;
                const float* bk = b + (isv ? 2 * CDIM : 0) + h * DHEAD;
                float s = 0.f;
#pragma unroll
                for (int d = 0; d < DHEAD; d++) s += bk[d] * M[(long)d * DHEAD];
                val = s;
            }
            g_bfv[idx] = val;
        }
        return;
    }
    bx -= NB_FB;
    {   // split x -> fp16 A operand
        int i = bx * 256 + threadIdx.x;
        if (i < N_NODES * CDIM / 4) {
            float4 v = ((const float4*)x)[i];
            __half2 a, b;
            a = __floats2half2_rn(v.x, v.y);
            b = __floats2half2_rn(v.z, v.w);
            ((__half2*)g_A16)[i * 2]     = a;
            ((__half2*)g_A16)[i * 2 + 1] = b;
        }
    }
}

// ===================== scan (re-zeroes g_deg for graph replay) ==============
__global__ void scan_kernel() {
    __shared__ int sh[1024];
    __shared__ int carry;
    int tid = threadIdx.x;
    if (tid == 0) { carry = 0; g_rowptr[0] = 0; }
    __syncthreads();
    for (int base = 0; base < N_NODES; base += 1024) {
        int i = base + tid;
        int v = (i < N_NODES) ? g_deg[i] : 0;
        if (i < N_NODES) g_deg[i] = 0;
        sh[tid] = v;
        __syncthreads();
        for (int off = 1; off < 1024; off <<= 1) {
            int t = (tid >= off) ? sh[tid - off] : 0;
            __syncthreads();
            sh[tid] += t;
            __syncthreads();
        }
        int inc = sh[tid] + carry;
        if (i < N_NODES) { g_rowptr[i + 1] = inc; g_cursor[i] = inc - v; }
        __syncthreads();
        if (tid == 1023) carry = inc;
        __syncthreads();
    }
}

__global__ void scatter_kernel(const int* __restrict__ ei0, const int* __restrict__ ei1) {
    int i = blockIdx.x * blockDim.x + threadIdx.x;
    if (i >= 2 * E_EDGES) return;
    int r = (i < E_EDGES) ? 0 : 1;
    int e = r ? (i - E_EDGES) : i;
    const int* ei = r ? ei1 : ei0;
    int src = ei[e];
    int dst = ei[E_EDGES + e];
    int pos = atomicAdd(&g_cursor[dst], 1);
    g_eadj[pos] = (src << 1) | r;
}

// ===================== mma.sync GEMM =========================================
// FULL3=false (GEMM1): fp16 1-term, stage=[Ah|Bh], proj epilogue (q fp32, kv fp16)
// FULL3=true  (GEMM2): bf16 3-term, stage=[Ah|Bh|Al|Bl], out epilogue (skip blend)
#define BK 64
#define SROWB 144
#define TILE_B (128 * SROWB)
#define SMEM_G1 (2 * 2 * TILE_B)
#define SMEM_G2 (2 * 4 * TILE_B)

template <bool FULL3>
__device__ __forceinline__ void load_stage(
    uint32_t smb, int buf,
    const uint16_t* Ah, const uint16_t* Al,
    const uint16_t* Bh, const uint16_t* Bl,
    int m0, int n0, int k0, int M, int tid)
{
    constexpr uint32_t STB = (FULL3 ? 4 : 2) * TILE_B;
    const uint32_t base = smb + buf * STB;
    const int c = tid & 7;
    const int r0 = tid >> 3;
#pragma unroll
    for (int q = 0; q < 4; q++) {
        int row = r0 + q * 32;
        uint32_t doff = (uint32_t)row * SROWB + c * 16;
        int grow = m0 + row;
        int va = (grow < M) ? 16 : 0;
        size_t aoff = ((size_t)(va ? grow : 0) * KTOT + k0) * 2 + c * 16;
        cpasync16(base + doff, (const char*)Ah + aoff, va);
        size_t boff = ((size_t)(n0 + row) * KTOT + k0) * 2 + c * 16;
        cpasync16(base + TILE_B + doff, (const char*)Bh + boff, 16);
        if (FULL3) {
            cpasync16(base + 2 * TILE_B + doff, (const char*)Al + aoff, va);
            cpasync16(base + 3 * TILE_B + doff, (const char*)Bl + boff, 16);
        }
    }
    asm volatile("cp.async.commit_group;" ::: "memory");
}

template <bool FULL3>
__global__ __launch_bounds__(256, FULL3 ? 1 : 2) void gemm_tc(
    const uint16_t* __restrict__ Ahp, const uint16_t* __restrict__ Alp,
    const uint16_t* __restrict__ Bhp, const uint16_t* __restrict__ Blp,
    const float* __restrict__ bias,
    int M, int Nn,
    float* __restrict__ Cout, const float* __restrict__ prev,
    const float* __restrict__ skipp,
    float* __restrict__ qOut, __half* __restrict__ kvOut)
{
    extern __shared__ char sm[];
    const uint32_t smb = smem_u32(sm);
    const int tid = threadIdx.x;
    const int wid = tid >> 5;
    const int lane = tid & 31;
    const int wrow = wid & 1;
    const int wcol = wid >> 1;
    const int m0 = blockIdx.y * 128;
    const int n0 = blockIdx.x * 128;
    constexpr uint32_t STB = (FULL3 ? 4 : 2) * TILE_B;

    float acc[4][4][4];
#pragma unroll
    for (int i = 0; i < 4; i++)
#pragma unroll
        for (int j = 0; j < 4; j++)
#pragma unroll
            for (int q = 0; q < 4; q++) acc[i][j][q] = 0.f;

    const int a_row = lane & 15;
    const int a_k8  = (lane >> 4) * 8;
    const int b_row = (lane & 7) | ((lane >> 4) << 3);
    const int b_k8  = ((lane >> 3) & 1) * 8;

    load_stage<FULL3>(smb, 0, Ahp, Alp, Bhp, Blp, m0, n0, 0, M, tid);

#pragma unroll
    for (int s = 0; s < 4; s++) {
        if (s < 3) load_stage<FULL3>(smb, (s + 1) & 1, Ahp, Alp, Bhp, Blp,
                                     m0, n0, (s + 1) * BK, M, tid);
        if (s < 3) asm volatile("cp.async.wait_group 1;" ::: "memory");
        else       asm volatile("cp.async.wait_group 0;" ::: "memory");
        __syncthreads();

        const uint32_t base = smb + (s & 1) * STB;
        const uint32_t aB = base + (uint32_t)(wrow * 64 + a_row) * SROWB + a_k8 * 2;
        const uint32_t bB = base + TILE_B + (uint32_t)(wcol * 32 + b_row) * SROWB + b_k8 * 2;

        if (FULL3) {
#pragma unroll
            for (int kk = 0; kk < BK / 16; kk++) {
                uint32_t Ah[4][4], Al[4][4];
#pragma unroll
                for (int mb = 0; mb < 4; mb++) {
                    uint32_t ad = aB + (uint32_t)mb * 16 * SROWB + kk * 32;
                    ldm_x4(Ah[mb], ad);
                    ldm_x4(Al[mb], ad + 2 * TILE_B);
                }
                uint32_t Bh[2][4], Bl[2][4];
#pragma unroll
                for (int nl = 0; nl < 2; nl++) {
                    uint32_t bd = bB + (uint32_t)nl * 16 * SROWB + kk * 32;
                    ldm_x4(Bh[nl], bd);
                    ldm_x4(Bl[nl], bd + 2 * TILE_B);
                }
#pragma unroll
                for (int mb = 0; mb < 4; mb++) {
#pragma unroll
                    for (int nb = 0; nb < 4; nb++) {
                        const uint32_t* bh = &Bh[nb >> 1][(nb & 1) * 2];
                        const uint32_t* bl = &Bl[nb >> 1][(nb & 1) * 2];
                        mma_bf16(acc[mb][nb], Ah[mb], bh);
                        mma_bf16(acc[mb][nb], Ah[mb], bl);
                        mma_bf16(acc[mb][nb], Al[mb], bh);
                    }
                }
            }
        } else {
#pragma unroll
            for (int kk = 0; kk < BK / 16; kk++) {
                uint32_t Ah[4][4];
#pragma unroll
                for (int mb = 0; mb < 4; mb++)
                    ldm_x4(Ah[mb], aB + (uint32_t)mb * 16 * SROWB + kk * 32);
                uint32_t Bh[2][4];
#pragma unroll
                for (int nl = 0; nl < 2; nl++)
                    ldm_x4(Bh[nl], bB + (uint32_t)nl * 16 * SROWB + kk * 32);
#pragma unroll
                for (int mb = 0; mb < 4; mb++)
#pragma unroll
                    for (int nb = 0; nb < 4; nb++)
                        mma_f16(acc[mb][nb], Ah[mb], &Bh[nb >> 1][(nb & 1) * 2]);
            }
        }
        __syncthreads();
    }

    // ---- epilogue ----
    float sc = 1.f, om = 0.f;
    if (FULL3) { float sk = *skipp; sc = 1.f / (1.f + __expf(-sk)); om = 1.f - sc; }

    const int lr = lane >> 2;
    const int lc = (lane & 3) * 2;
#pragma unroll
    for (int mb = 0; mb < 4; mb++) {
#pragma unroll
        for (int half = 0; half < 2; half++) {
            int grow = m0 + wrow * 64 + mb * 16 + lr + half * 8;
            if (grow >= M) continue;
#pragma unroll
            for (int nb = 0; nb < 4; nb++) {
                int gcol = n0 + wcol * 32 + nb * 8 + lc;
                float v0 = acc[mb][nb][half * 2 + 0] + bias[gcol];
                float v1 = acc[mb][nb][half * 2 + 1] + bias[gcol + 1];
                if (FULL3) {
                    const float2 pv = *(const float2*)(prev + (size_t)grow * Nn + gcol);
                    v0 = sc * v0 + om * pv.x;
                    v1 = sc * v1 + om * pv.y;
                    *(float2*)(Cout + (size_t)grow * Nn + gcol) = make_float2(v0, v1);
                } else {
                    if (gcol < CDIM) {
                        *(float2*)(qOut + (size_t)grow * CDIM + gcol) = make_float2(v0, v1);
                    } else {
                        int t = gcol - CDIM;
                        int sec = t >> 8;               // 0,1: k r0/r1; 2,3: v r0/r1
                        int off = t & 255;
                        int dst = (sec & 1) * 512 + (sec >> 1) * 256 + off;
                        *(__half2*)(kvOut + (size_t)grow * 1024 + dst) =
                            __floats2half2_rn(v0, v1);
                    }
                }
            }
        }
    }
}

// ================ edge aggregation: warp per dst, online softmax ============
struct OState {
    float m, ssum;
    float acc[8];
};

__device__ __forceinline__ void edge_step(
    OState& st, uint4 kr, uint4 vr, float pr, const float* q)
{
    float2 k0 = __half22float2(*(__half2*)&kr.x);
    float2 k1 = __half22float2(*(__half2*)&kr.y);
    float2 k2 = __half22float2(*(__half2*)&kr.z);
    float2 k3 = __half22float2(*(__half2*)&kr.w);
    float d = q[0] * k0.x + q[1] * k0.y + q[2] * k1.x + q[3] * k1.y
            + q[4] * k2.x + q[5] * k2.y + q[6] * k3.x + q[7] * k3.y;
    d += __shfl_xor_sync(0xffffffffu, d, 1);
    d += __shfl_xor_sync(0xffffffffu, d, 2);
    float lg = d * pr;
    float nm = fmaxf(st.m, lg);
    float cf = __expf(st.m - nm);
    float pw = __expf(lg - nm);
    st.ssum = st.ssum * cf + pw;
    st.m = nm;
    float2 v0 = __half22float2(*(__half2*)&vr.x);
    float2 v1 = __half22float2(*(__half2*)&vr.y);
    float2 v2 = __half22float2(*(__half2*)&vr.z);
    float2 v3 = __half22float2(*(__half2*)&vr.w);
    st.acc[0] = st.acc[0] * cf + pw * v0.x;
    st.acc[1] = st.acc[1] * cf + pw * v0.y;
    st.acc[2] = st.acc[2] * cf + pw * v1.x;
    st.acc[3] = st.acc[3] * cf + pw * v1.y;
    st.acc[4] = st.acc[4] * cf + pw * v2.x;
    st.acc[5] = st.acc[5] * cf + pw * v2.y;
    st.acc[6] = st.acc[6] * cf + pw * v3.x;
    st.acc[7] = st.acc[7] * cf + pw * v3.y;
}

__global__ __launch_bounds__(256) void edge_agg(const float* __restrict__ prel_l) {
    int warp = (blockIdx.x * blockDim.x + threadIdx.x) >> 5;
    int lane = threadIdx.x & 31;
    if (warp >= N_NODES) return;
    const int n = warp;
    const int h = lane >> 2;
    const int d8 = (lane & 3) * 8;
    const int hoff = h * DHEAD + d8;

    float q[8];
    *(float4*)(q)     = *(const float4*)(g_Q + (size_t)n * CDIM + hoff);
    *(float4*)(q + 4) = *(const float4*)(g_Q + (size_t)n * CDIM + hoff + 4);
    const float scale = 0.17677669529663687f;  // 1/sqrt(32)
    const float p0 = prel_l[h] * scale;
    const float p1 = prel_l[HHEADS + h] * scale;

    OState st;
    st.m = -INFINITY; st.ssum = 0.f;
#pragma unroll
    for (int i = 0; i < 8; i++) st.acc[i] = 0.f;

    const int e0 = g_rowptr[n], e1 = g_rowptr[n + 1];
    int e = e0;
    for (; e + 2 <= e1; e += 2) {
        int pk0 = g_eadj[e];
        int pk1 = g_eadj[e + 1];
        const __half* b0 = g_KV + ((size_t)(pk0 >> 1) * 1024 + (pk0 & 1) * 512 + hoff);
        const __half* b1 = g_KV + ((size_t)(pk1 >> 1) * 1024 + (pk1 & 1) * 512 + hoff);
        uint4 k0 = __ldg((const uint4*)b0);
        uint4 v0 = __ldg((const uint4*)(b0 + 256));
        uint4 k1 = __ldg((const uint4*)b1);
        uint4 v1 = __ldg((const uint4*)(b1 + 256));
        edge_step(st, k0, v0, (pk0 & 1) ? p1 : p0, q);
        edge_step(st, k1, v1, (pk1 & 1) ? p1 : p0, q);
    }
    if (e < e1) {
        int pk = g_eadj[e];
        const __half* b = g_KV + ((size_t)(pk >> 1) * 1024 + (pk & 1) * 512 + hoff);
        uint4 kr = __ldg((const uint4*)b);
        uint4 vr = __ldg((const uint4*)(b + 256));
        edge_step(st, kr, vr, (pk & 1) ? p1 : p0, q);
    }

    float inv = 1.0f / fmaxf(st.ssum, 1e-16f);
    uint4 uh, ul;
    __nv_bfloat162* ph = (__nv_bfloat162*)&uh;
    __nv_bfloat162* pl = (__nv_bfloat162*)&ul;
#pragma unroll
    for (int i = 0; i < 4; i++) {
        float x0 = st.acc[2 * i] * inv;
        float x1 = st.acc[2 * i + 1] * inv;
        float g0 = 0.5f * x0 * (1.0f + erff(x0 * 0.70710678118654752f));
        float g1 = 0.5f * x1 * (1.0f + erff(x1 * 0.70710678118654752f));
        __nv_bfloat16 h0 = __float2bfloat16(g0);
        __nv_bfloat16 h1 = __float2bfloat16(g1);
        ph[i].x = h0; ph[i].y = h1;
        pl[i].x = __float2bfloat16(g0 - __bfloat162float(h0));
        pl[i].y = __float2bfloat16(g1 - __bfloat162float(h1));
    }
    *(uint4*)(g_Ahi + (size_t)n * CDIM + hoff) = uh;
    *(uint4*)(g_Alo + (size_t)n * CDIM + hoff) = ul;
}

// ================ fused relu + layernorm + fp16 store =======================
__global__ __launch_bounds__(256) void relu_ln(float* __restrict__ hbuf,
                                               const float* __restrict__ g,
                                               const float* __restrict__ b) {
    int warp = (blockIdx.x * blockDim.x + threadIdx.x) >> 5;
    int lane = threadIdx.x & 31;
    if (warp >= N_NODES) return;
    float* row = hbuf + (size_t)warp * CDIM;
    float v[8];
    *(float4*)(v)     = *(const float4*)(row + lane * 8);
    *(float4*)(v + 4) = *(const float4*)(row + lane * 8 + 4);
    float s = 0.f, s2 = 0.f;
#pragma unroll
    for (int i = 0; i < 8; i++) {
        v[i] = fmaxf(v[i], 0.f);
        s += v[i];
        s2 += v[i] * v[i];
    }
#pragma unroll
    for (int off = 16; off > 0; off >>= 1) {
        s += __shfl_xor_sync(0xffffffffu, s, off);
        s2 += __shfl_xor_sync(0xffffffffu, s2, off);
    }
    float mu = s * (1.f / CDIM);
    float var = s2 * (1.f / CDIM) - mu * mu;
    float rs = rsqrtf(var + 1e-5f);
#pragma unroll
    for (int i = 0; i < 8; i++) {
        int c = lane * 8 + i;
        v[i] = (v[i] - mu) * rs * g[c] + b[c];
    }
    uint4 u16;
    __half2* p16 = (__half2*)&u16;
#pragma unroll
    for (int i = 0; i < 4; i++)
        p16[i] = __floats2half2_rn(v[2 * i], v[2 * i + 1]);
    *(float4*)(row + lane * 8)     = *(const float4*)(v);
    *(float4*)(row + lane * 8 + 4) = *(const float4*)(v + 4);
    *(uint4*)(g_A16 + (size_t)warp * CDIM + lane * 8) = u16;
}

// ===================== launch ================================================
extern "C" void kernel_launch(void* const* d_in, const int* in_sizes, int n_in,
                              void* d_out, int out_size) {
    const float* x      = (const float*)d_in[0];
    const int*   ei0    = (const int*)d_in[1];
    const int*   ei1    = (const int*)d_in[2];
    const float* kqv_w  = (const float*)d_in[3];
    const float* kqv_b  = (const float*)d_in[4];
    const float* out_w  = (const float*)d_in[5];
    const float* out_b  = (const float*)d_in[6];
    const float* skip   = (const float*)d_in[7];
    const float* krel   = (const float*)d_in[8];
    const float* vrel   = (const float*)d_in[9];
    const float* prel   = (const float*)d_in[10];
    const float* ln_g   = (const float*)d_in[11];
    const float* ln_b   = (const float*)d_in[12];
    float* out = (float*)d_out;

    cudaFuncSetAttribute(gemm_tc<false>, cudaFuncAttributeMaxDynamicSharedMemorySize, SMEM_G1);
    cudaFuncSetAttribute(gemm_tc<true>,  cudaFuncAttributeMaxDynamicSharedMemorySize, SMEM_G2);

    float *hA, *hB, *bf, *Q;
    __half *W1h, *A16, *KV;
    __nv_bfloat16 *W2h, *W2l, *Ah, *Al;
    cudaGetSymbolAddress((void**)&hA, g_hA);
    cudaGetSymbolAddress((void**)&hB, g_hB);
    cudaGetSymbolAddress((void**)&bf, g_bfv);
    cudaGetSymbolAddress((void**)&Q, g_Q);
    cudaGetSymbolAddress((void**)&KV, g_KV);
    cudaGetSymbolAddress((void**)&W1h, g_W1h);
    cudaGetSymbolAddress((void**)&W2h, g_W2hi);
    cudaGetSymbolAddress((void**)&W2l, g_W2lo);
    cudaGetSymbolAddress((void**)&A16, g_A16);
    cudaGetSymbolAddress((void**)&Ah, g_Ahi);
    cudaGetSymbolAddress((void**)&Al, g_Alo);

    fat_pre<<<NB_TOTAL, 256>>>(ei0, ei1, kqv_w, kqv_b, out_w, krel, vrel, x);
    scan_kernel<<<1, 1024>>>();
    scatter_kernel<<<(2 * E_EDGES + 255) / 256, 256>>>(ei0, ei1);

    const int MT = (N_NODES + 127) / 128;  // 157
    const float* hin = x;

    for (int l = 0; l < L_LAYERS; l++) {
        float* hout = (l == 3) ? out : ((l % 2 == 0) ? hA : hB);

        // GEMM1 (fp16 1-term): [q fp32 | kv fp16] = A16 @ W1^T + bias
        gemm_tc<false><<<dim3(PCOLS / 128, MT), 256, SMEM_G1>>>(
            (const uint16_t*)A16, nullptr,
            (const uint16_t*)(W1h + (size_t)l * PCOLS * CDIM), nullptr,
            bf + (size_t)l * PCOLS, N_NODES, PCOLS,
            nullptr, nullptr, nullptr, Q, KV);

        // edge aggregation + softmax + gelu -> Ahi/Alo (bf16 split)
        edge_agg<<<(N_NODES * 32) / 256, 256>>>(prel + (size_t)l * R_REL * HHEADS);

        // GEMM2 (bf16 3-term): hout = s*(G @ W2^T + out_b) + (1-s)*hin
        gemm_tc<true><<<dim3(CDIM / 128, MT), 256, SMEM_G2>>>(
            (const uint16_t*)Ah, (const uint16_t*)Al,
            (const uint16_t*)(W2h + (size_t)l * CDIM * CDIM),
            (const uint16_t*)(W2l + (size_t)l * CDIM * CDIM),
            out_b + (size_t)l * CDIM, N_NODES, CDIM,
            hout, hin, skip + l, nullptr, nullptr);

        if (l < L_LAYERS - 1) {
            relu_ln<<<(N_NODES * 32) / 256, 256>>>(hout, ln_g + (size_t)l * CDIM,
                                                   ln_b + (size_t)l * CDIM);
        }
        hin = hout;
    }
}

// round 6
// speedup vs baseline: 3.4699x; 1.1581x over previous
#include <cuda_runtime.h>
#include <cuda_bf16.h>
#include <cuda_fp16.h>
#include <math.h>
#include <stdint.h>

#define N_NODES 20000
#define CDIM 256
#define HHEADS 8
#define DHEAD 32
#define E_EDGES 160000
#define L_LAYERS 4
#define R_REL 2
#define PCOLS 1280   // q(256) | k_r0(256) | k_r1(256) | v_r0(256) | v_r1(256)
#define KTOT 256

// ===================== scratch (device globals) =============================
__device__ float g_Q[(size_t)N_NODES * CDIM];                      // q fp32
__device__ __half g_KV[(size_t)N_NODES * 1024];                    // [n][r][k256|v256] fp16
__device__ float g_hA[(size_t)N_NODES * CDIM];
__device__ float g_hB[(size_t)N_NODES * CDIM];
__device__ float g_bfv[(size_t)L_LAYERS * PCOLS];
__device__ __half g_W1h[(size_t)L_LAYERS * PCOLS * CDIM];          // [l][n][k] fp16
__device__ __half g_W2h[(size_t)L_LAYERS * CDIM * CDIM];           // [l][n][k] fp16
__device__ __half g_A16[(size_t)N_NODES * CDIM];                   // shared A (fp16)
__device__ int g_deg[N_NODES];
__device__ int g_rowptr[N_NODES + 1];
__device__ int g_cursor[N_NODES];
__device__ int g_eadj[2 * E_EDGES];

// ===================== small PTX helpers ====================================
__device__ __forceinline__ uint32_t smem_u32(const void* p) {
    uint32_t a;
    asm("{ .reg .u64 t; cvta.to.shared.u64 t, %1; cvt.u32.u64 %0, t; }"
        : "=r"(a) : "l"(p));
    return a;
}
__device__ __forceinline__ void cpasync16(uint32_t dst, const void* src, int src_sz) {
    asm volatile("cp.async.cg.shared.global [%0], [%1], 16, %2;"
                 :: "r"(dst), "l"(src), "r"(src_sz));
}
__device__ __forceinline__ void ldm_x4(uint32_t* r, uint32_t addr) {
    asm volatile("ldmatrix.sync.aligned.m8n8.x4.shared.b16 {%0,%1,%2,%3}, [%4];"
                 : "=r"(r[0]), "=r"(r[1]), "=r"(r[2]), "=r"(r[3]) : "r"(addr));
}
__device__ __forceinline__ void mma_f16(float* c, const uint32_t* a, const uint32_t* b) {
    asm volatile("mma.sync.aligned.m16n8k16.row.col.f32.f16.f16.f32 "
                 "{%0,%1,%2,%3}, {%4,%5,%6,%7}, {%8,%9}, {%0,%1,%2,%3};"
                 : "+f"(c[0]), "+f"(c[1]), "+f"(c[2]), "+f"(c[3])
                 : "r"(a[0]), "r"(a[1]), "r"(a[2]), "r"(a[3]),
                   "r"(b[0]), "r"(b[1]));
}

// ===================== fused preprocess (fat kernel) =========================
#define NB_HIST 1250
#define NB_FW1 5120
#define NB_FW2 1024
#define NB_FB 20
#define NB_SPLIT 5000
#define NB_TOTAL (NB_HIST + NB_FW1 + NB_FW2 + NB_FB + NB_SPLIT)

__device__ __forceinline__ float fold_w1_val(long idx, const float* kqv_w,
                                             const float* krel, const float* vrel) {
    int j = (int)(idx % PCOLS);
    int c = (int)((idx / PCOLS) % CDIM);
    int l = (int)(idx / ((long)PCOLS * CDIM));
    const float* W = kqv_w + ((long)l * CDIM + c) * (3 * CDIM);
    if (j < CDIM) return W[CDIM + j];  // q (split order k,q,v)
    int jj = j - CDIM;
    int sec = jj >> 8;
    int r = sec & 1;
    int isv = sec >> 1;
    int hf = jj & 255;
    int h = hf >> 5, f = hf & 31;
    const float* M = (isv ? vrel : krel) +
                     ((((long)l * R_REL + r) * HHEADS + h) * DHEAD) * DHEAD + f;
    const float* wk = W + (isv ? 2 * CDIM : 0) + h * DHEAD;
    float s = 0.f;
#pragma unroll
    for (int d = 0; d < DHEAD; d++) s += wk[d] * M[(long)d * DHEAD];
    return s;
}

__global__ __launch_bounds__(256) void fat_pre(
    const int* __restrict__ ei0, const int* __restrict__ ei1,
    const float* __restrict__ kqv_w, const float* __restrict__ kqv_b,
    const float* __restrict__ out_w,
    const float* __restrict__ krel, const float* __restrict__ vrel,
    const float* __restrict__ x)
{
    int bx = blockIdx.x;
    if (bx < NB_HIST) {
        int i = bx * 256 + threadIdx.x;
        if (i < 2 * E_EDGES) {
            int dst = (i < E_EDGES) ? ei0[E_EDGES + i] : ei1[E_EDGES + (i - E_EDGES)];
            atomicAdd(&g_deg[dst], 1);
        }
        return;
    }
    bx -= NB_HIST;
    if (bx < NB_FW1) {
        long idx = (long)bx * 256 + threadIdx.x;
        float val = fold_w1_val(idx, kqv_w, krel, vrel);
        int j = (int)(idx % PCOLS);
        int c = (int)((idx / PCOLS) % CDIM);
        int l = (int)(idx / ((long)PCOLS * CDIM));
        g_W1h[((long)l * PCOLS + j) * CDIM + c] = __float2half_rn(val);
        return;
    }
    bx -= NB_FW1;
    if (bx < NB_FW2) {
        long idx = (long)bx * 256 + threadIdx.x;
        int n = (int)(idx & 255);
        int k = (int)((idx >> 8) & 255);
        int l = (int)(idx >> 16);
        float val = out_w[((long)l * CDIM + k) * CDIM + n];
        g_W2h[((long)l * CDIM + n) * CDIM + k] = __float2half_rn(val);
        return;
    }
    bx -= NB_FW2;
    if (bx < NB_FB) {
        int idx = bx * 256 + threadIdx.x;
        if (idx < L_LAYERS * PCOLS) {
            int j = idx % PCOLS;
            int l = idx / PCOLS;
            const float* b = kqv_b + (long)l * 3 * CDIM;
            float val;
            if (j < CDIM) {
                val = b[CDIM + j];
            } else {
                int jj = j - CDIM;
                int sec = jj >> 8;
                int r = sec & 1;
                int isv = sec >> 1;
                int hf = jj & 255;
                int h = hf >> 5, f = hf & 31;
                const float* M = (isv ? vrel : krel) +
                                 ((((long)l * R_REL + r) * HHEADS + h) * DHEAD) * DHEAD + f;
                const float* bk = b + (isv ? 2 * CDIM : 0) + h * DHEAD;
                float s = 0.f;
#pragma unroll
                for (int d = 0; d < DHEAD; d++) s += bk[d] * M[(long)d * DHEAD];
                val = s;
            }
            g_bfv[idx] = val;
        }
        return;
    }
    bx -= NB_FB;
    {   // x -> fp16 A operand
        int i = bx * 256 + threadIdx.x;
        if (i < N_NODES * CDIM / 4) {
            float4 v = ((const float4*)x)[i];
            ((__half2*)g_A16)[i * 2]     = __floats2half2_rn(v.x, v.y);
            ((__half2*)g_A16)[i * 2 + 1] = __floats2half2_rn(v.z, v.w);
        }
    }
}

// ===================== scan (re-zeroes g_deg for graph replay) ==============
__global__ void scan_kernel() {
    __shared__ int sh[1024];
    __shared__ int carry;
    int tid = threadIdx.x;
    if (tid == 0) { carry = 0; g_rowptr[0] = 0; }
    __syncthreads();
    for (int base = 0; base < N_NODES; base += 1024) {
        int i = base + tid;
        int v = (i < N_NODES) ? g_deg[i] : 0;
        if (i < N_NODES) g_deg[i] = 0;
        sh[tid] = v;
        __syncthreads();
        for (int off = 1; off < 1024; off <<= 1) {
            int t = (tid >= off) ? sh[tid - off] : 0;
            __syncthreads();
            sh[tid] += t;
            __syncthreads();
        }
        int inc = sh[tid] + carry;
        if (i < N_NODES) { g_rowptr[i + 1] = inc; g_cursor[i] = inc - v; }
        __syncthreads();
        if (tid == 1023) carry = inc;
        __syncthreads();
    }
}

__global__ void scatter_kernel(const int* __restrict__ ei0, const int* __restrict__ ei1) {
    int i = blockIdx.x * blockDim.x + threadIdx.x;
    if (i >= 2 * E_EDGES) return;
    int r = (i < E_EDGES) ? 0 : 1;
    int e = r ? (i - E_EDGES) : i;
    const int* ei = r ? ei1 : ei0;
    int src = ei[e];
    int dst = ei[E_EDGES + e];
    int pos = atomicAdd(&g_cursor[dst], 1);
    g_eadj[pos] = (src << 1) | r;
}

// ===================== fp16 mma.sync GEMM (1-term) ===========================
// C[M x Nn] = A16[M x 256] @ B16^T ([n][k]) ; CTA 128x128, 8 warps, BK=64, 2-buf
// mode 0 (qOut!=null): proj epilogue -> q fp32 (cols<256), kv fp16 (cols>=256)
// mode 1: out epilogue -> Cout fp32 = s*(acc+bias) + (1-s)*prev
#define BK 64
#define SROWB 144
#define TILE_B (128 * SROWB)
#define STAGE_B (2 * TILE_B)
#define GEMM_SMEM (2 * STAGE_B)

__device__ __forceinline__ void load_stage(
    uint32_t smb, int buf, const __half* A, const __half* B,
    int m0, int n0, int k0, int M, int tid)
{
    const uint32_t base = smb + buf * STAGE_B;
    const int c = tid & 7;
    const int r0 = tid >> 3;
#pragma unroll
    for (int q = 0; q < 4; q++) {
        int row = r0 + q * 32;
        uint32_t doff = (uint32_t)row * SROWB + c * 16;
        int grow = m0 + row;
        int va = (grow < M) ? 16 : 0;
        size_t aoff = ((size_t)(va ? grow : 0) * KTOT + k0) * 2 + c * 16;
        cpasync16(base + doff, (const char*)A + aoff, va);
        size_t boff = ((size_t)(n0 + row) * KTOT + k0) * 2 + c * 16;
        cpasync16(base + TILE_B + doff, (const char*)B + boff, 16);
    }
    asm volatile("cp.async.commit_group;" ::: "memory");
}

__global__ __launch_bounds__(256, 2) void gemm_f16(
    const __half* __restrict__ A, const __half* __restrict__ B,
    const float* __restrict__ bias,
    int M, int Nn,
    float* __restrict__ Cout, const float* __restrict__ prev,
    const float* __restrict__ skipp,
    float* __restrict__ qOut, __half* __restrict__ kvOut)
{
    extern __shared__ char sm[];
    const uint32_t smb = smem_u32(sm);
    const int tid = threadIdx.x;
    const int wid = tid >> 5;
    const int lane = tid & 31;
    const int wrow = wid & 1;
    const int wcol = wid >> 1;
    const int m0 = blockIdx.y * 128;
    const int n0 = blockIdx.x * 128;

    float acc[4][4][4];
#pragma unroll
    for (int i = 0; i < 4; i++)
#pragma unroll
        for (int j = 0; j < 4; j++)
#pragma unroll
            for (int q = 0; q < 4; q++) acc[i][j][q] = 0.f;

    const int a_row = lane & 15;
    const int a_k8  = (lane >> 4) * 8;
    const int b_row = (lane & 7) | ((lane >> 4) << 3);
    const int b_k8  = ((lane >> 3) & 1) * 8;

    load_stage(smb, 0, A, B, m0, n0, 0, M, tid);

#pragma unroll
    for (int s = 0; s < 4; s++) {
        if (s < 3) load_stage(smb, (s + 1) & 1, A, B, m0, n0, (s + 1) * BK, M, tid);
        if (s < 3) asm volatile("cp.async.wait_group 1;" ::: "memory");
        else       asm volatile("cp.async.wait_group 0;" ::: "memory");
        __syncthreads();

        const uint32_t base = smb + (s & 1) * STAGE_B;
        const uint32_t aB = base + (uint32_t)(wrow * 64 + a_row) * SROWB + a_k8 * 2;
        const uint32_t bB = base + TILE_B + (uint32_t)(wcol * 32 + b_row) * SROWB + b_k8 * 2;

#pragma unroll
        for (int kk = 0; kk < BK / 16; kk++) {
            uint32_t Ar[4][4];
#pragma unroll
            for (int mb = 0; mb < 4; mb++)
                ldm_x4(Ar[mb], aB + (uint32_t)mb * 16 * SROWB + kk * 32);
            uint32_t Br[2][4];
#pragma unroll
            for (int nl = 0; nl < 2; nl++)
                ldm_x4(Br[nl], bB + (uint32_t)nl * 16 * SROWB + kk * 32);
#pragma unroll
            for (int mb = 0; mb < 4; mb++)
#pragma unroll
                for (int nb = 0; nb < 4; nb++)
                    mma_f16(acc[mb][nb], Ar[mb], &Br[nb >> 1][(nb & 1) * 2]);
        }
        __syncthreads();
    }

    // ---- epilogue ----
    const bool projmode = (qOut != nullptr);
    float sc = 1.f, om = 0.f;
    if (!projmode) { float sk = *skipp; sc = 1.f / (1.f + __expf(-sk)); om = 1.f - sc; }

    const int lr = lane >> 2;
    const int lc = (lane & 3) * 2;
#pragma unroll
    for (int mb = 0; mb < 4; mb++) {
#pragma unroll
        for (int half = 0; half < 2; half++) {
            int grow = m0 + wrow * 64 + mb * 16 + lr + half * 8;
            if (grow >= M) continue;
#pragma unroll
            for (int nb = 0; nb < 4; nb++) {
                int gcol = n0 + wcol * 32 + nb * 8 + lc;
                float v0 = acc[mb][nb][half * 2 + 0] + bias[gcol];
                float v1 = acc[mb][nb][half * 2 + 1] + bias[gcol + 1];
                if (!projmode) {
                    const float2 pv = *(const float2*)(prev + (size_t)grow * Nn + gcol);
                    v0 = sc * v0 + om * pv.x;
                    v1 = sc * v1 + om * pv.y;
                    *(float2*)(Cout + (size_t)grow * Nn + gcol) = make_float2(v0, v1);
                } else {
                    if (gcol < CDIM) {
                        *(float2*)(qOut + (size_t)grow * CDIM + gcol) = make_float2(v0, v1);
                    } else {
                        int t = gcol - CDIM;
                        int sec = t >> 8;               // 0,1: k r0/r1; 2,3: v r0/r1
                        int off = t & 255;
                        int dst = (sec & 1) * 512 + (sec >> 1) * 256 + off;
                        *(__half2*)(kvOut + (size_t)grow * 1024 + dst) =
                            __floats2half2_rn(v0, v1);
                    }
                }
            }
        }
    }
}

// ================ edge aggregation: warp per dst, online softmax ============
struct OState {
    float m, ssum;
    float acc[8];
};

__device__ __forceinline__ void edge_step(
    OState& st, uint4 kr, uint4 vr, float pr, const float* q)
{
    float2 k0 = __half22float2(*(__half2*)&kr.x);
    float2 k1 = __half22float2(*(__half2*)&kr.y);
    float2 k2 = __half22float2(*(__half2*)&kr.z);
    float2 k3 = __half22float2(*(__half2*)&kr.w);
    float d = q[0] * k0.x + q[1] * k0.y + q[2] * k1.x + q[3] * k1.y
            + q[4] * k2.x + q[5] * k2.y + q[6] * k3.x + q[7] * k3.y;
    d += __shfl_xor_sync(0xffffffffu, d, 1);
    d += __shfl_xor_sync(0xffffffffu, d, 2);
    float lg = d * pr;
    float nm = fmaxf(st.m, lg);
    float cf = __expf(st.m - nm);
    float pw = __expf(lg - nm);
    st.ssum = st.ssum * cf + pw;
    st.m = nm;
    float2 v0 = __half22float2(*(__half2*)&vr.x);
    float2 v1 = __half22float2(*(__half2*)&vr.y);
    float2 v2 = __half22float2(*(__half2*)&vr.z);
    float2 v3 = __half22float2(*(__half2*)&vr.w);
    st.acc[0] = st.acc[0] * cf + pw * v0.x;
    st.acc[1] = st.acc[1] * cf + pw * v0.y;
    st.acc[2] = st.acc[2] * cf + pw * v1.x;
    st.acc[3] = st.acc[3] * cf + pw * v1.y;
    st.acc[4] = st.acc[4] * cf + pw * v2.x;
    st.acc[5] = st.acc[5] * cf + pw * v2.y;
    st.acc[6] = st.acc[6] * cf + pw * v3.x;
    st.acc[7] = st.acc[7] * cf + pw * v3.y;
}

__global__ __launch_bounds__(256) void edge_agg(const float* __restrict__ prel_l) {
    int warp = (blockIdx.x * blockDim.x + threadIdx.x) >> 5;
    int lane = threadIdx.x & 31;
    if (warp >= N_NODES) return;
    const int n = warp;
    const int h = lane >> 2;
    const int d8 = (lane & 3) * 8;
    const int hoff = h * DHEAD + d8;

    float q[8];
    *(float4*)(q)     = *(const float4*)(g_Q + (size_t)n * CDIM + hoff);
    *(float4*)(q + 4) = *(const float4*)(g_Q + (size_t)n * CDIM + hoff + 4);
    const float scale = 0.17677669529663687f;  // 1/sqrt(32)
    const float p0 = prel_l[h] * scale;
    const float p1 = prel_l[HHEADS + h] * scale;

    OState st;
    st.m = -INFINITY; st.ssum = 0.f;
#pragma unroll
    for (int i = 0; i < 8; i++) st.acc[i] = 0.f;

    const int e0 = g_rowptr[n], e1 = g_rowptr[n + 1];
    int e = e0;
    // 4-wide unrolled gather: 8 outstanding 16B loads before any compute
    for (; e + 4 <= e1; e += 4) {
        int pk[4];
        uint4 kr[4], vr[4];
#pragma unroll
        for (int j = 0; j < 4; j++) pk[j] = g_eadj[e + j];
#pragma unroll
        for (int j = 0; j < 4; j++) {
            const __half* b = g_KV + ((size_t)(pk[j] >> 1) * 1024 + (pk[j] & 1) * 512 + hoff);
            kr[j] = __ldg((const uint4*)b);
            vr[j] = __ldg((const uint4*)(b + 256));
        }
#pragma unroll
        for (int j = 0; j < 4; j++)
            edge_step(st, kr[j], vr[j], (pk[j] & 1) ? p1 : p0, q);
    }
    for (; e < e1; e++) {
        int pk = g_eadj[e];
        const __half* b = g_KV + ((size_t)(pk >> 1) * 1024 + (pk & 1) * 512 + hoff);
        uint4 kr = __ldg((const uint4*)b);
        uint4 vr = __ldg((const uint4*)(b + 256));
        edge_step(st, kr, vr, (pk & 1) ? p1 : p0, q);
    }

    float inv = 1.0f / fmaxf(st.ssum, 1e-16f);
    uint4 u16;
    __half2* p16 = (__half2*)&u16;
#pragma unroll
    for (int i = 0; i < 4; i++) {
        float x0 = st.acc[2 * i] * inv;
        float x1 = st.acc[2 * i + 1] * inv;
        float g0 = 0.5f * x0 * (1.0f + erff(x0 * 0.70710678118654752f));
        float g1 = 0.5f * x1 * (1.0f + erff(x1 * 0.70710678118654752f));
        p16[i] = __floats2half2_rn(g0, g1);
    }
    *(uint4*)(g_A16 + (size_t)n * CDIM + hoff) = u16;
}

// ================ fused relu + layernorm + fp16 store =======================
__global__ __launch_bounds__(256) void relu_ln(float* __restrict__ hbuf,
                                               const float* __restrict__ g,
                                               const float* __restrict__ b) {
    int warp = (blockIdx.x * blockDim.x + threadIdx.x) >> 5;
    int lane = threadIdx.x & 31;
    if (warp >= N_NODES) return;
    float* row = hbuf + (size_t)warp * CDIM;
    float v[8];
    *(float4*)(v)     = *(const float4*)(row + lane * 8);
    *(float4*)(v + 4) = *(const float4*)(row + lane * 8 + 4);
    float s = 0.f, s2 = 0.f;
#pragma unroll
    for (int i = 0; i < 8; i++) {
        v[i] = fmaxf(v[i], 0.f);
        s += v[i];
        s2 += v[i] * v[i];
    }
#pragma unroll
    for (int off = 16; off > 0; off >>= 1) {
        s += __shfl_xor_sync(0xffffffffu, s, off);
        s2 += __shfl_xor_sync(0xffffffffu, s2, off);
    }
    float mu = s * (1.f / CDIM);
    float var = s2 * (1.f / CDIM) - mu * mu;
    float rs = rsqrtf(var + 1e-5f);
#pragma unroll
    for (int i = 0; i < 8; i++) {
        int c = lane * 8 + i;
        v[i] = (v[i] - mu) * rs * g[c] + b[c];
    }
    uint4 u16;
    __half2* p16 = (__half2*)&u16;
#pragma unroll
    for (int i = 0; i < 4; i++)
        p16[i] = __floats2half2_rn(v[2 * i], v[2 * i + 1]);
    *(float4*)(row + lane * 8)     = *(const float4*)(v);
    *(float4*)(row + lane * 8 + 4) = *(const float4*)(v + 4);
    *(uint4*)(g_A16 + (size_t)warp * CDIM + lane * 8) = u16;
}

// ===================== launch ================================================
extern "C" void kernel_launch(void* const* d_in, const int* in_sizes, int n_in,
                              void* d_out, int out_size) {
    const float* x      = (const float*)d_in[0];
    const int*   ei0    = (const int*)d_in[1];
    const int*   ei1    = (const int*)d_in[2];
    const float* kqv_w  = (const float*)d_in[3];
    const float* kqv_b  = (const float*)d_in[4];
    const float* out_w  = (const float*)d_in[5];
    const float* out_b  = (const float*)d_in[6];
    const float* skip   = (const float*)d_in[7];
    const float* krel   = (const float*)d_in[8];
    const float* vrel   = (const float*)d_in[9];
    const float* prel   = (const float*)d_in[10];
    const float* ln_g   = (const float*)d_in[11];
    const float* ln_b   = (const float*)d_in[12];
    float* out = (float*)d_out;

    cudaFuncSetAttribute(gemm_f16, cudaFuncAttributeMaxDynamicSharedMemorySize, GEMM_SMEM);

    float *hA, *hB, *bf, *Q;
    __half *W1h, *W2h, *A16, *KV;
    cudaGetSymbolAddress((void**)&hA, g_hA);
    cudaGetSymbolAddress((void**)&hB, g_hB);
    cudaGetSymbolAddress((void**)&bf, g_bfv);
    cudaGetSymbolAddress((void**)&Q, g_Q);
    cudaGetSymbolAddress((void**)&KV, g_KV);
    cudaGetSymbolAddress((void**)&W1h, g_W1h);
    cudaGetSymbolAddress((void**)&W2h, g_W2h);
    cudaGetSymbolAddress((void**)&A16, g_A16);

    fat_pre<<<NB_TOTAL, 256>>>(ei0, ei1, kqv_w, kqv_b, out_w, krel, vrel, x);
    scan_kernel<<<1, 1024>>>();
    scatter_kernel<<<(2 * E_EDGES + 255) / 256, 256>>>(ei0, ei1);

    const int MT = (N_NODES + 127) / 128;  // 157
    const float* hin = x;

    for (int l = 0; l < L_LAYERS; l++) {
        float* hout = (l == 3) ? out : ((l % 2 == 0) ? hA : hB);

        // GEMM1 (fp16): [q fp32 | kv fp16] = A16 @ W1^T + bias
        gemm_f16<<<dim3(PCOLS / 128, MT), 256, GEMM_SMEM>>>(
            A16, W1h + (size_t)l * PCOLS * CDIM,
            bf + (size_t)l * PCOLS, N_NODES, PCOLS,
            nullptr, nullptr, nullptr, Q, KV);

        // edge aggregation + softmax + gelu -> A16 (fp16)
        edge_agg<<<(N_NODES * 32) / 256, 256>>>(prel + (size_t)l * R_REL * HHEADS);

        // GEMM2 (fp16): hout = s*(A16 @ W2^T + out_b) + (1-s)*hin
        gemm_f16<<<dim3(CDIM / 128, MT), 256, GEMM_SMEM>>>(
            A16, W2h + (size_t)l * CDIM * CDIM,
            out_b + (size_t)l * CDIM, N_NODES, CDIM,
            hout, hin, skip + l, nullptr, nullptr);

        if (l < L_LAYERS - 1) {
            relu_ln<<<(N_NODES * 32) / 256, 256>>>(hout, ln_g + (size_t)l * CDIM,
                                                   ln_b + (size_t)l * CDIM);
        }
        hin = hout;
    }
}